// round 3
// baseline (speedup 1.0000x reference)
#include <cuda_runtime.h>
#include <math.h>
#include <stdint.h>

#define BSZ 512
#define ENT 512
#define SEQN 64
#define DK 32
#define DF 256
#define DIN 1024
#define NGATE 128
#define ENP1 513

// ----------------------------- static scratch --------------------------------
__device__ float g_key[(size_t)BSZ * ENT * DK];        // keys (+ end scatter)
__device__ int   g_removed[(size_t)BSZ * ENP1];        // first removal step (j+1); 65 = never
__device__ float g_selemb[(size_t)SEQN * BSZ * DK];    // pooled emb after step j
__device__ float g_base[(size_t)BSZ * DF];             // ar@q1 + q1_b
__device__ float g_W2[(size_t)DF * DF];                // e2@q1
__device__ float g_c2[DF];                             // e2_b@q1
__device__ float g_u[(size_t)(SEQN - 1) * BSZ * DF];   // relu(selemb@e1+e1_b)
__device__ float g_P[(size_t)(SEQN - 1) * BSZ * DF];   // u @ W2
__device__ float g_x[(size_t)SEQN * BSZ * DK];         // LSTM inputs
__device__ float g_gx[(size_t)SEQN * BSZ * NGATE];     // LN(x@w_ih)
__device__ float g_q[(size_t)SEQN * BSZ * DK];         // queries (h per step)

__device__ __forceinline__ float wredsum(float v) {
#pragma unroll
    for (int o = 16; o; o >>= 1) v += __shfl_xor_sync(0xffffffffu, v, o);
    return v;
}

// ------------------- key GEMM: [BSZ*ENT,256]@[256,32] + scatter ---------------
__global__ void k_key(const float* __restrict__ ent, const float* __restrict__ W,
                      const float* __restrict__ bias, const float* __restrict__ endv,
                      const int* __restrict__ en_arr) {
    __shared__ float4 Ash4[64 * 8];
    __shared__ float Wsh[32 * 32];
    int t = threadIdx.x;
    size_t row0 = (size_t)blockIdx.x * 64;
    int b = (int)(row0 >> 9);
    int en = en_arr[b];
    int tx = t & 31, ty = t >> 5;
    float acc[8];
#pragma unroll
    for (int rr = 0; rr < 8; rr++) acc[rr] = 0.f;
    const float4* A4 = (const float4*)ent;
    for (int k0 = 0; k0 < 256; k0 += 32) {
#pragma unroll
        for (int p = 0; p < 2; p++) {
            int idx = t + p * 256;
            int r = idx >> 3, c4 = idx & 7;
            Ash4[r * 8 + c4] = A4[(row0 + r) * 64 + (k0 >> 2) + c4];
        }
#pragma unroll
        for (int p = 0; p < 4; p++) {
            int idx = t + p * 256;
            int k = idx >> 5, cc = idx & 31;
            Wsh[k * 32 + cc] = W[(size_t)(k0 + k) * 32 + cc];
        }
        __syncthreads();
#pragma unroll
        for (int k4 = 0; k4 < 8; k4++) {
            float w0 = Wsh[(k4 * 4 + 0) * 32 + tx];
            float w1 = Wsh[(k4 * 4 + 1) * 32 + tx];
            float w2 = Wsh[(k4 * 4 + 2) * 32 + tx];
            float w3 = Wsh[(k4 * 4 + 3) * 32 + tx];
#pragma unroll
            for (int rr = 0; rr < 8; rr++) {
                float4 a = Ash4[(ty * 8 + rr) * 8 + k4];
                acc[rr] += a.x * w0 + a.y * w1 + a.z * w2 + a.w * w3;
            }
        }
        __syncthreads();
    }
    float bv = bias[tx], ev = endv[tx];
    int e0 = (int)(row0 & 511);
#pragma unroll
    for (int rr = 0; rr < 8; rr++) {
        int e = e0 + ty * 8 + rr;
        g_key[(row0 + ty * 8 + rr) * 32 + tx] = (e == en) ? ev : (acc[rr] + bv);
    }
}

// ------------------- first-removal-step scatter --------------------------------
__global__ void k_removed(const int* __restrict__ sel) {
    int b = blockIdx.x;
    for (int n = threadIdx.x; n < ENP1; n += blockDim.x) g_removed[(size_t)b * ENP1 + n] = 65;
    __syncthreads();
    if (threadIdx.x < SEQN) {
        int s = sel[b * SEQN + threadIdx.x];
        atomicMin(&g_removed[(size_t)b * ENP1 + s], threadIdx.x + 1);
    }
}

// ------------------- per-step pooled embedding (warp/batch) --------------------
__global__ void k_emb(const int* __restrict__ sel, const int* __restrict__ en_arr,
                      const int* __restrict__ selnum) {
    int t = threadIdx.x;
    int lane = t & 31;
    int b = blockIdx.x * 8 + (t >> 5);
    int en = en_arr[b];
    int sn = selnum[b];
    float sum = 0.f;
    int cnt = 0;
    bool endf = false;
    for (int j = 0; j < SEQN; j++) {
        int s = sel[b * SEQN + j];
        endf = endf || (s == en);
        bool add = (!endf) && (g_removed[(size_t)b * ENP1 + s] == j + 1);
        if (add) {
            sum += g_key[((size_t)b * ENT + s) * DK + lane];
            cnt++;
        }
        float denom = (sn != 0 && cnt > 0) ? (float)cnt : 1.f;
        g_selemb[((size_t)j * BSZ + b) * DK + lane] = sum / denom;
    }
}

// ------------------- c2 = e2_b @ q1_w ------------------------------------------
__global__ void k_c2(const float* __restrict__ e2b, const float* __restrict__ q1w) {
    int t = threadIdx.x;
    float acc = 0.f;
    for (int k = 0; k < DIN; k++) acc += e2b[k] * q1w[(size_t)k * DF + t];
    g_c2[t] = acc;
}

// ------------------- generic tiled SGEMM: C = A@B (+bias), tiles 64x64x16 ------
__global__ void k_sgemm(const float* __restrict__ A, const float* __restrict__ B,
                        const float* __restrict__ bias, float* __restrict__ C,
                        int M, int K, int N) {
    __shared__ float As[16][64];
    __shared__ float Bs[16][64];
    int t = threadIdx.x;
    int tx = t & 15, ty = t >> 4;
    int m0 = blockIdx.x * 64, n0 = blockIdx.y * 64;
    float acc[4][4];
#pragma unroll
    for (int i = 0; i < 4; i++)
#pragma unroll
        for (int j = 0; j < 4; j++) acc[i][j] = 0.f;

    for (int k0 = 0; k0 < K; k0 += 16) {
        {
            int r = t >> 2, kk = (t & 3) * 4;
            float4 a = *(const float4*)&A[(size_t)(m0 + r) * K + k0 + kk];
            As[kk + 0][r] = a.x;
            As[kk + 1][r] = a.y;
            As[kk + 2][r] = a.z;
            As[kk + 3][r] = a.w;
        }
        {
            int kr = t >> 4, nn = (t & 15) * 4;
            *(float4*)&Bs[kr][nn] = *(const float4*)&B[(size_t)(k0 + kr) * N + n0 + nn];
        }
        __syncthreads();
#pragma unroll
        for (int k = 0; k < 16; k++) {
            float av[4], bv[4];
            *(float4*)av = *(const float4*)&As[k][ty * 4];
            *(float4*)bv = *(const float4*)&Bs[k][tx * 4];
#pragma unroll
            for (int i = 0; i < 4; i++)
#pragma unroll
                for (int j = 0; j < 4; j++) acc[i][j] += av[i] * bv[j];
        }
        __syncthreads();
    }
    float bb[4];
#pragma unroll
    for (int j = 0; j < 4; j++) bb[j] = bias ? bias[n0 + tx * 4 + j] : 0.f;
#pragma unroll
    for (int i = 0; i < 4; i++) {
        float4 o;
        o.x = acc[i][0] + bb[0];
        o.y = acc[i][1] + bb[1];
        o.z = acc[i][2] + bb[2];
        o.w = acc[i][3] + bb[3];
        *(float4*)&C[(size_t)(m0 + ty * 4 + i) * N + n0 + tx * 4] = o;
    }
}

// ------------------- u = relu(selemb @ e1 + e1_b): [63*512,32]@[32,256] --------
__global__ void k_u(const float* __restrict__ e1w, const float* __restrict__ e1b) {
    __shared__ float Ash[128 * 32];
    int t = threadIdx.x;
    size_t row0 = (size_t)blockIdx.x * 128;
    float breg[32];
#pragma unroll
    for (int k = 0; k < 32; k++) breg[k] = e1w[k * 256 + t];
    for (int idx = t; idx < 128 * 32; idx += 256) Ash[idx] = g_selemb[row0 * 32 + idx];
    __syncthreads();
    float bias = e1b[t];
    for (int r = 0; r < 128; r++) {
        float acc = bias;
#pragma unroll
        for (int k = 0; k < 32; k++) acc += Ash[r * 32 + k] * breg[k];
        g_u[(row0 + r) * 256 + t] = fmaxf(acc, 0.f);
    }
}

// ------------------- x_i = relu(base [+c2+P]) @ q2 + q2_b ----------------------
__global__ void k_x(const float* __restrict__ q2w, const float* __restrict__ q2b) {
    __shared__ float Wsh[256 * 32];
    __shared__ float Ash[8 * 256];
    int t = threadIdx.x;
    for (int idx = t; idx < 8192; idx += 256) Wsh[idx] = q2w[idx];
    size_t row0 = (size_t)blockIdx.x * 8;
    int i = (int)(row0 >> 9);
    for (int idx = t; idx < 2048; idx += 256) {
        int r = idx >> 8, k = idx & 255;
        size_t row = row0 + r;
        int b = (int)(row & 511);
        float pre = g_base[(size_t)b * 256 + k];
        if (i > 0) pre += g_c2[k] + g_P[(row - 512) * 256 + k];
        Ash[idx] = fmaxf(pre, 0.f);
    }
    __syncthreads();
    int tx = t & 31, ty = t >> 5;
    float acc = q2b[tx];
#pragma unroll 8
    for (int k = 0; k < 256; k++) acc += Ash[ty * 256 + k] * Wsh[k * 32 + tx];
    g_x[(row0 + ty) * 32 + tx] = acc;
}

// ------------------- gx = LN(x @ w_ih; ln_ig, ln_ib) ---------------------------
__global__ void k_gx(const float* __restrict__ wih, const float* __restrict__ ln_ig,
                     const float* __restrict__ ln_ib) {
    __shared__ float wsh[32 * 128];
    int t = threadIdx.x;
    for (int idx = t; idx < 4096; idx += 256) wsh[idx] = wih[idx];
    __syncthreads();
    int lane = t & 31, w = t >> 5;
    size_t row = (size_t)blockIdx.x * 8 + w;
    float xv = g_x[row * 32 + lane];
    float acc[4];
#pragma unroll
    for (int g = 0; g < 4; g++) acc[g] = 0.f;
#pragma unroll
    for (int k = 0; k < 32; k++) {
        float xk = __shfl_sync(0xffffffffu, xv, k);
#pragma unroll
        for (int g = 0; g < 4; g++) acc[g] += xk * wsh[k * 128 + g * 32 + lane];
    }
    float s = acc[0] + acc[1] + acc[2] + acc[3];
    float m = wredsum(s) * (1.f / 128.f);
    float vs = 0.f;
#pragma unroll
    for (int g = 0; g < 4; g++) {
        float d = acc[g] - m;
        vs += d * d;
    }
    float v = wredsum(vs) * (1.f / 128.f);
    float rs = rsqrtf(v + 1e-5f);
#pragma unroll
    for (int g = 0; g < 4; g++) {
        int c = g * 32 + lane;
        g_gx[row * 128 + c] = (acc[g] - m) * rs * ln_ig[c] + ln_ib[c];
    }
}

// ------------------- sequential LN-LSTM (warp/batch) ---------------------------
__global__ void k_lstm(const float* __restrict__ whh, const float* __restrict__ ln_hg,
                       const float* __restrict__ ln_hb, const float* __restrict__ ln_cg,
                       const float* __restrict__ ln_cb) {
    __shared__ float wsh[32 * 128];
    int t = threadIdx.x;
    for (int idx = t; idx < 4096; idx += 256) wsh[idx] = whh[idx];
    __syncthreads();
    int lane = t & 31, w = t >> 5;
    int b = blockIdx.x * 8 + w;
    float h = 0.f, c = 0.f;
    float hg[4], hb[4];
#pragma unroll
    for (int g = 0; g < 4; g++) {
        int cc = g * 32 + lane;
        hg[g] = ln_hg[cc];
        hb[g] = ln_hb[cc];
    }
    float cgm = ln_cg[lane], cbm = ln_cb[lane];
    for (int i = 0; i < SEQN; i++) {
        size_t row = (size_t)i * BSZ + b;
        float acc[4];
#pragma unroll
        for (int g = 0; g < 4; g++) acc[g] = 0.f;
#pragma unroll
        for (int k = 0; k < 32; k++) {
            float hk = __shfl_sync(0xffffffffu, h, k);
#pragma unroll
            for (int g = 0; g < 4; g++) acc[g] += hk * wsh[k * 128 + g * 32 + lane];
        }
        float s = acc[0] + acc[1] + acc[2] + acc[3];
        float m = wredsum(s) * (1.f / 128.f);
        float vs = 0.f;
#pragma unroll
        for (int g = 0; g < 4; g++) {
            float d = acc[g] - m;
            vs += d * d;
        }
        float v = wredsum(vs) * (1.f / 128.f);
        float rs = rsqrtf(v + 1e-5f);
        float gate[4];
#pragma unroll
        for (int g = 0; g < 4; g++)
            gate[g] = g_gx[row * 128 + g * 32 + lane] + (acc[g] - m) * rs * hg[g] + hb[g];
        float ii = 1.f / (1.f + __expf(-gate[0]));
        float ff = 1.f / (1.f + __expf(-gate[1]));
        float gg = tanhf(gate[2]);
        float oo = 1.f / (1.f + __expf(-gate[3]));
        float cn = ff * c + ii * gg;
        float mc = wredsum(cn) * (1.f / 32.f);
        float dc = cn - mc;
        float vc = wredsum(dc * dc) * (1.f / 32.f);
        c = dc * rsqrtf(vc + 1e-5f) * cgm + cbm;
        h = oo * tanhf(c);
        g_q[row * 32 + lane] = h;
    }
}

// ------------------- logits + mask ---------------------------------------------
__global__ void k_logits(const int* __restrict__ en_arr, float* __restrict__ out) {
    __shared__ float Qsh[64 * 32];
    __shared__ float Ksh[256 * 33];
    __shared__ int rsh[256];
    int t = threadIdx.x;
    int b = blockIdx.x;
    int en = en_arr[b];
    for (int idx = t; idx < 2048; idx += 256) {
        int s = idx >> 5, k = idx & 31;
        Qsh[idx] = g_q[((size_t)s * BSZ + b) * 32 + k];
    }
    for (int tile = 0; tile < 2; tile++) {
        int n0 = tile * 256;
        __syncthreads();
        for (int idx = t; idx < 8192; idx += 256) {
            int n = idx >> 5, k = idx & 31;
            Ksh[n * 33 + k] = g_key[((size_t)b * ENT + n0 + n) * 32 + k];
        }
        rsh[t] = g_removed[(size_t)b * ENP1 + n0 + t];
        __syncthreads();
        float kreg[32];
#pragma unroll
        for (int k = 0; k < 32; k++) kreg[k] = Ksh[t * 33 + k];
        int rstep = rsh[t];
        int n = n0 + t;
        for (int s = 0; s < SEQN; s++) {
            float dot = 0.f;
#pragma unroll
            for (int k = 0; k < 32; k++) dot += Qsh[s * 32 + k] * kreg[k];
            bool keep = (n < en) ? (rstep > s) : ((n == en) ? (s >= 1 && rstep > s) : false);
            out[((size_t)b * SEQN + s) * ENP1 + n] = keep ? dot : -1e9f;
        }
    }
    if (t < SEQN) out[((size_t)b * SEQN + t) * ENP1 + 512] = -1e9f;
}

// ------------------------------- launch ----------------------------------------
extern "C" void kernel_launch(void* const* d_in, const int* in_sizes, int n_in,
                              void* d_out, int out_size) {
    const float* ent = (const float*)d_in[0];
    const float* ar = (const float*)d_in[1];
    const int* entity_num = (const int*)d_in[2];
    const int* sel = (const int*)d_in[3];
    const int* selnum = (const int*)d_in[4];
    const float* key_w = (const float*)d_in[5];
    const float* key_b = (const float*)d_in[6];
    const float* q1w = (const float*)d_in[7];
    const float* q1b = (const float*)d_in[8];
    const float* q2w = (const float*)d_in[9];
    const float* q2b = (const float*)d_in[10];
    const float* e1w = (const float*)d_in[11];
    const float* e1b = (const float*)d_in[12];
    const float* e2w = (const float*)d_in[13];
    const float* e2b = (const float*)d_in[14];
    const float* endv = (const float*)d_in[15];
    const float* wih = (const float*)d_in[16];
    const float* whh = (const float*)d_in[17];
    const float* ln_ig = (const float*)d_in[18];
    const float* ln_ib = (const float*)d_in[19];
    const float* ln_hg = (const float*)d_in[20];
    const float* ln_hb = (const float*)d_in[21];
    const float* ln_cg = (const float*)d_in[22];
    const float* ln_cb = (const float*)d_in[23];
    float* out = (float*)d_out;

    void *pBase, *pW2, *pU, *pP;
    cudaGetSymbolAddress(&pBase, g_base);
    cudaGetSymbolAddress(&pW2, g_W2);
    cudaGetSymbolAddress(&pU, g_u);
    cudaGetSymbolAddress(&pP, g_P);

    // independent preambles
    k_key<<<4096, 256>>>(ent, key_w, key_b, endv, entity_num);
    k_removed<<<BSZ, 256>>>(sel);
    k_c2<<<1, 256>>>(e2b, q1w);
    k_sgemm<<<dim3(BSZ / 64, DF / 64), 256>>>(ar, q1w, q1b, (float*)pBase, BSZ, DIN, DF);
    k_sgemm<<<dim3(DF / 64, DF / 64), 256>>>(e2w, q1w, nullptr, (float*)pW2, DF, DIN, DF);
    // pooled embeddings (needs key + removed)
    k_emb<<<BSZ / 8, 256>>>(sel, entity_num, selnum);
    // u = relu(selemb@e1+e1_b); P = u@W2
    k_u<<<(SEQN - 1) * BSZ / 128, 256>>>(e1w, e1b);
    k_sgemm<<<dim3((SEQN - 1) * BSZ / 64, DF / 64), 256>>>((const float*)pU, (const float*)pW2,
                                                           nullptr, (float*)pP,
                                                           (SEQN - 1) * BSZ, DF, DF);
    // x, gx, lstm, logits
    k_x<<<SEQN * BSZ / 8, 256>>>(q2w, q2b);
    k_gx<<<SEQN * BSZ / 8, 256>>>(wih, ln_ig, ln_ib);
    k_lstm<<<BSZ / 8, 256>>>(whh, ln_hg, ln_hb, ln_cg, ln_cb);
    k_logits<<<BSZ, 256>>>(entity_num, out);
    (void)in_sizes;
    (void)n_in;
    (void)out_size;
}

// round 4
// speedup vs baseline: 1.1075x; 1.1075x over previous
#include <cuda_runtime.h>
#include <math.h>
#include <stdint.h>

#define BSZ 512
#define ENT 512
#define SEQN 64
#define DK 32
#define DF 256
#define DIN 1024
#define NGATE 128
#define ENP1 513
#define BK 16

typedef unsigned long long u64;

// ----------------------------- static scratch --------------------------------
__device__ float g_key[(size_t)BSZ * ENT * DK];        // keys (+ end scatter)
__device__ int   g_removed[(size_t)BSZ * ENP1];        // first removal step (j+1); 65 = never
__device__ float g_selemb[(size_t)SEQN * BSZ * DK];    // pooled emb after step j
__device__ float g_base[(size_t)BSZ * DF];             // ar@q1 + q1_b (raw)
__device__ float g_W2[(size_t)DF * DF];                // e2@q1
__device__ float g_c2[DF];                             // e2_b@q1
__device__ float g_u[(size_t)(SEQN - 1) * BSZ * DF];   // relu(selemb@e1+e1_b)
__device__ float g_R[(size_t)SEQN * BSZ * DF];         // relu(pre-activation) all steps
__device__ float g_x[(size_t)SEQN * BSZ * DK];         // LSTM inputs
__device__ float g_gx[(size_t)SEQN * BSZ * NGATE];     // LN(x@w_ih)
__device__ float g_q[(size_t)SEQN * BSZ * DK];         // queries (h per step)

// ----------------------------- helpers ---------------------------------------
__device__ __forceinline__ float wredsum(float v) {
#pragma unroll
    for (int o = 16; o; o >>= 1) v += __shfl_xor_sync(0xffffffffu, v, o);
    return v;
}
__device__ __forceinline__ u64 pk2(float x) {
    u64 r;
    asm("mov.b64 %0,{%1,%1};" : "=l"(r) : "f"(x));
    return r;
}
__device__ __forceinline__ void fma2(u64& d, u64 a, u64 b) {
    asm("fma.rn.f32x2 %0,%1,%2,%0;" : "+l"(d) : "l"(a), "l"(b));
}
__device__ __forceinline__ float2 up2(u64 v) {
    float2 f;
    asm("mov.b64 {%0,%1},%2;" : "=f"(f.x), "=f"(f.y) : "l"(v));
    return f;
}

// ----------------------------- generic FFMA2 GEMM ----------------------------
// C[M,N] = A[M,K] @ B[K,N] with epilogue variants.
// EPI: 0 = plain        -> C
//      1 = +bias        -> C
//      2 = +bias, end-embedding scatter (key)       -> C
//      3 = +bias -> C; relu -> C2 (base GEMM)
//      4 = +xb[b]+xc, relu -> C2 at row+BSZ (P GEMM)
//      5 = relu(+bias)  -> C (u GEMM)
template <int TM, int TN, int RM, int EPI>
__global__ void k_gemm(const float* __restrict__ A, const float* __restrict__ B,
                       const float* __restrict__ bias, float* __restrict__ C,
                       int K, int N,
                       const float* __restrict__ xb, const float* __restrict__ xc,
                       const int* __restrict__ xi, float* __restrict__ C2) {
    __shared__ float As[BK * TM];   // k-major
    __shared__ float Bs[BK * TN];   // k-major
    const int t = threadIdx.x;
    const int NT4 = TN / 4;
    const int tx = t % NT4;
    const int ty = t / NT4;
    const int m0 = blockIdx.x * TM;
    const int n0 = blockIdx.y * TN;

    u64 acc[RM][2];
#pragma unroll
    for (int r = 0; r < RM; r++) {
        acc[r][0] = 0ull;
        acc[r][1] = 0ull;
    }

    for (int k0 = 0; k0 < K; k0 += BK) {
        // stage A (transposed to k-major)
        constexpr int ALOADS = TM * BK / 4;
#pragma unroll
        for (int idx = t; idx < ALOADS; idx += 256) {
            int r = idx >> 2;
            int kk = (idx & 3) * 4;
            float4 a = *(const float4*)&A[(size_t)(m0 + r) * K + k0 + kk];
            As[(kk + 0) * TM + r] = a.x;
            As[(kk + 1) * TM + r] = a.y;
            As[(kk + 2) * TM + r] = a.z;
            As[(kk + 3) * TM + r] = a.w;
        }
        // stage B (row-major within chunk)
        constexpr int BLOADS = TN * BK / 4;
#pragma unroll
        for (int idx = t; idx < BLOADS; idx += 256) {
            int kr = idx / NT4;
            int nn = (idx % NT4) * 4;
            *(float4*)&Bs[kr * TN + nn] = *(const float4*)&B[(size_t)(k0 + kr) * N + n0 + nn];
        }
        __syncthreads();
#pragma unroll
        for (int k = 0; k < BK; k++) {
            u64 ap[RM];
            if (RM == 4) {
                float4 av = *(const float4*)&As[k * TM + ty * 4];
                ap[0] = pk2(av.x);
                ap[1] = pk2(av.y);
                ap[2] = pk2(av.z);
                ap[3] = pk2(av.w);
            } else {
                float2 av = *(const float2*)&As[k * TM + ty * 2];
                ap[0] = pk2(av.x);
                ap[1] = pk2(av.y);
            }
            ulonglong2 bv = *(const ulonglong2*)&Bs[k * TN + tx * 4];
#pragma unroll
            for (int r = 0; r < RM; r++) {
                fma2(acc[r][0], ap[r], bv.x);
                fma2(acc[r][1], ap[r], bv.y);
            }
        }
        __syncthreads();
    }

    float bb[4] = {0.f, 0.f, 0.f, 0.f};
    if (EPI == 1 || EPI == 2 || EPI == 3 || EPI == 5) {
        float4 b4 = *(const float4*)&bias[n0 + tx * 4];
        bb[0] = b4.x;
        bb[1] = b4.y;
        bb[2] = b4.z;
        bb[3] = b4.w;
    }
#pragma unroll
    for (int r = 0; r < RM; r++) {
        int m = m0 + ty * RM + r;
        int c0 = n0 + tx * 4;
        float2 lo = up2(acc[r][0]);
        float2 hi = up2(acc[r][1]);
        float v[4] = {lo.x, lo.y, hi.x, hi.y};
        if (EPI == 0) {
            *(float4*)&C[(size_t)m * N + c0] = make_float4(v[0], v[1], v[2], v[3]);
        } else if (EPI == 1) {
            *(float4*)&C[(size_t)m * N + c0] =
                make_float4(v[0] + bb[0], v[1] + bb[1], v[2] + bb[2], v[3] + bb[3]);
        } else if (EPI == 2) {
            int en = xi[m >> 9];
            float4 o;
            if ((m & 511) == en) {
                o = *(const float4*)&xb[c0];
            } else {
                o = make_float4(v[0] + bb[0], v[1] + bb[1], v[2] + bb[2], v[3] + bb[3]);
            }
            *(float4*)&C[(size_t)m * N + c0] = o;
        } else if (EPI == 3) {
            float4 o = make_float4(v[0] + bb[0], v[1] + bb[1], v[2] + bb[2], v[3] + bb[3]);
            *(float4*)&C[(size_t)m * N + c0] = o;
            *(float4*)&C2[(size_t)m * N + c0] =
                make_float4(fmaxf(o.x, 0.f), fmaxf(o.y, 0.f), fmaxf(o.z, 0.f), fmaxf(o.w, 0.f));
        } else if (EPI == 4) {
            int b = m & 511;
            float4 bs = *(const float4*)&xb[(size_t)b * N + c0];
            float4 cc = *(const float4*)&xc[c0];
            *(float4*)&C2[(size_t)(m + BSZ) * N + c0] =
                make_float4(fmaxf(v[0] + bs.x + cc.x, 0.f), fmaxf(v[1] + bs.y + cc.y, 0.f),
                            fmaxf(v[2] + bs.z + cc.z, 0.f), fmaxf(v[3] + bs.w + cc.w, 0.f));
        } else if (EPI == 5) {
            *(float4*)&C[(size_t)m * N + c0] =
                make_float4(fmaxf(v[0] + bb[0], 0.f), fmaxf(v[1] + bb[1], 0.f),
                            fmaxf(v[2] + bb[2], 0.f), fmaxf(v[3] + bb[3], 0.f));
        }
    }
}

// ------------------- first-removal-step scatter --------------------------------
__global__ void k_removed(const int* __restrict__ sel) {
    int b = blockIdx.x;
    for (int n = threadIdx.x; n < ENP1; n += blockDim.x) g_removed[(size_t)b * ENP1 + n] = 65;
    __syncthreads();
    if (threadIdx.x < SEQN) {
        int s = sel[b * SEQN + threadIdx.x];
        atomicMin(&g_removed[(size_t)b * ENP1 + s], threadIdx.x + 1);
    }
}

// ------------------- per-step pooled embedding (warp/batch) --------------------
__global__ void k_emb(const int* __restrict__ sel, const int* __restrict__ en_arr,
                      const int* __restrict__ selnum) {
    int t = threadIdx.x;
    int lane = t & 31;
    int b = blockIdx.x * 8 + (t >> 5);
    int en = en_arr[b];
    int sn = selnum[b];
    float sum = 0.f;
    int cnt = 0;
    bool endf = false;
    for (int j = 0; j < SEQN; j++) {
        int s = sel[b * SEQN + j];
        endf = endf || (s == en);
        bool add = (!endf) && (g_removed[(size_t)b * ENP1 + s] == j + 1);
        if (add) {
            sum += g_key[((size_t)b * ENT + s) * DK + lane];
            cnt++;
        }
        float denom = (sn != 0 && cnt > 0) ? (float)cnt : 1.f;
        g_selemb[((size_t)j * BSZ + b) * DK + lane] = sum / denom;
    }
}

// ------------------- c2 = e2_b @ q1_w ------------------------------------------
__global__ void k_c2(const float* __restrict__ e2b, const float* __restrict__ q1w) {
    int t = threadIdx.x;
    float acc = 0.f;
    for (int k = 0; k < DIN; k++) acc += e2b[k] * q1w[(size_t)k * DF + t];
    g_c2[t] = acc;
}

// ------------------- gx = LN(x @ w_ih; ln_ig, ln_ib) ---------------------------
__global__ void k_gx(const float* __restrict__ wih, const float* __restrict__ ln_ig,
                     const float* __restrict__ ln_ib) {
    __shared__ float wsh[32 * 128];
    int t = threadIdx.x;
    for (int idx = t; idx < 4096; idx += 256) wsh[idx] = wih[idx];
    __syncthreads();
    int lane = t & 31, w = t >> 5;
    size_t row = (size_t)blockIdx.x * 8 + w;
    float xv = g_x[row * 32 + lane];
    float acc[4];
#pragma unroll
    for (int g = 0; g < 4; g++) acc[g] = 0.f;
#pragma unroll
    for (int k = 0; k < 32; k++) {
        float xk = __shfl_sync(0xffffffffu, xv, k);
#pragma unroll
        for (int g = 0; g < 4; g++) acc[g] += xk * wsh[k * 128 + g * 32 + lane];
    }
    float s = acc[0] + acc[1] + acc[2] + acc[3];
    float m = wredsum(s) * (1.f / 128.f);
    float vs = 0.f;
#pragma unroll
    for (int g = 0; g < 4; g++) {
        float d = acc[g] - m;
        vs += d * d;
    }
    float v = wredsum(vs) * (1.f / 128.f);
    float rs = rsqrtf(v + 1e-5f);
#pragma unroll
    for (int g = 0; g < 4; g++) {
        int c = g * 32 + lane;
        g_gx[row * 128 + c] = (acc[g] - m) * rs * ln_ig[c] + ln_ib[c];
    }
}

// ------------------- sequential LN-LSTM (warp/batch) ---------------------------
__global__ void k_lstm(const float* __restrict__ whh, const float* __restrict__ ln_hg,
                       const float* __restrict__ ln_hb, const float* __restrict__ ln_cg,
                       const float* __restrict__ ln_cb) {
    __shared__ float wsh[32 * 128];
    int t = threadIdx.x;
    for (int idx = t; idx < 4096; idx += 256) wsh[idx] = whh[idx];
    __syncthreads();
    int lane = t & 31, w = t >> 5;
    int b = blockIdx.x * 8 + w;
    float h = 0.f, c = 0.f;
    float hg[4], hb[4];
#pragma unroll
    for (int g = 0; g < 4; g++) {
        int cc = g * 32 + lane;
        hg[g] = ln_hg[cc];
        hb[g] = ln_hb[cc];
    }
    float cgm = ln_cg[lane], cbm = ln_cb[lane];
    for (int i = 0; i < SEQN; i++) {
        size_t row = (size_t)i * BSZ + b;
        float acc[4];
#pragma unroll
        for (int g = 0; g < 4; g++) acc[g] = 0.f;
#pragma unroll
        for (int k = 0; k < 32; k++) {
            float hk = __shfl_sync(0xffffffffu, h, k);
#pragma unroll
            for (int g = 0; g < 4; g++) acc[g] += hk * wsh[k * 128 + g * 32 + lane];
        }
        float s = acc[0] + acc[1] + acc[2] + acc[3];
        float m = wredsum(s) * (1.f / 128.f);
        float vs = 0.f;
#pragma unroll
        for (int g = 0; g < 4; g++) {
            float d = acc[g] - m;
            vs += d * d;
        }
        float v = wredsum(vs) * (1.f / 128.f);
        float rs = rsqrtf(v + 1e-5f);
        float gate[4];
#pragma unroll
        for (int g = 0; g < 4; g++)
            gate[g] = g_gx[row * 128 + g * 32 + lane] + (acc[g] - m) * rs * hg[g] + hb[g];
        float ii = 1.f / (1.f + __expf(-gate[0]));
        float ff = 1.f / (1.f + __expf(-gate[1]));
        float gg = tanhf(gate[2]);
        float oo = 1.f / (1.f + __expf(-gate[3]));
        float cn = ff * c + ii * gg;
        float mc = wredsum(cn) * (1.f / 32.f);
        float dc = cn - mc;
        float vc = wredsum(dc * dc) * (1.f / 32.f);
        c = dc * rsqrtf(vc + 1e-5f) * cgm + cbm;
        h = oo * tanhf(c);
        g_q[row * 32 + lane] = h;
    }
}

// ------------------- logits + mask (FFMA2 dot products) -------------------------
__global__ void k_logits(const int* __restrict__ en_arr, float* __restrict__ out) {
    __shared__ float Qsh[64 * 32];
    __shared__ float Ksh[256 * 34];
    __shared__ int rsh[256];
    int t = threadIdx.x;
    int b = blockIdx.x;
    int en = en_arr[b];
    for (int idx = t; idx < 2048; idx += 256) {
        int s = idx >> 5, k = idx & 31;
        Qsh[idx] = g_q[((size_t)s * BSZ + b) * 32 + k];
    }
    const u64* Q2 = (const u64*)Qsh;
    for (int tile = 0; tile < 2; tile++) {
        int n0 = tile * 256;
        __syncthreads();
        for (int idx = t; idx < 8192; idx += 256) {
            int n = idx >> 5, k = idx & 31;
            Ksh[n * 34 + k] = g_key[((size_t)b * ENT + n0 + n) * 32 + k];
        }
        rsh[t] = g_removed[(size_t)b * ENP1 + n0 + t];
        __syncthreads();
        u64 kreg[16];
#pragma unroll
        for (int kp = 0; kp < 16; kp++) {
            float2 kk = *(const float2*)&Ksh[t * 34 + kp * 2];
            asm("mov.b64 %0,{%1,%2};" : "=l"(kreg[kp]) : "f"(kk.x), "f"(kk.y));
        }
        int rstep = rsh[t];
        int n = n0 + t;
        for (int s = 0; s < SEQN; s++) {
            u64 a0 = 0ull, a1 = 0ull;
#pragma unroll
            for (int kp = 0; kp < 16; kp += 2) {
                fma2(a0, kreg[kp], Q2[s * 16 + kp]);
                fma2(a1, kreg[kp + 1], Q2[s * 16 + kp + 1]);
            }
            float2 f0 = up2(a0), f1 = up2(a1);
            float dot = (f0.x + f0.y) + (f1.x + f1.y);
            bool keep = (n < en) ? (rstep > s) : ((n == en) ? (s >= 1 && rstep > s) : false);
            out[((size_t)b * SEQN + s) * ENP1 + n] = keep ? dot : -1e9f;
        }
    }
    if (t < SEQN) out[((size_t)b * SEQN + t) * ENP1 + 512] = -1e9f;
}

// ------------------------------- launch ----------------------------------------
extern "C" void kernel_launch(void* const* d_in, const int* in_sizes, int n_in,
                              void* d_out, int out_size) {
    const float* ent = (const float*)d_in[0];
    const float* ar = (const float*)d_in[1];
    const int* entity_num = (const int*)d_in[2];
    const int* sel = (const int*)d_in[3];
    const int* selnum = (const int*)d_in[4];
    const float* key_w = (const float*)d_in[5];
    const float* key_b = (const float*)d_in[6];
    const float* q1w = (const float*)d_in[7];
    const float* q1b = (const float*)d_in[8];
    const float* q2w = (const float*)d_in[9];
    const float* q2b = (const float*)d_in[10];
    const float* e1w = (const float*)d_in[11];
    const float* e1b = (const float*)d_in[12];
    const float* e2w = (const float*)d_in[13];
    const float* e2b = (const float*)d_in[14];
    const float* endv = (const float*)d_in[15];
    const float* wih = (const float*)d_in[16];
    const float* whh = (const float*)d_in[17];
    const float* ln_ig = (const float*)d_in[18];
    const float* ln_ib = (const float*)d_in[19];
    const float* ln_hg = (const float*)d_in[20];
    const float* ln_hb = (const float*)d_in[21];
    const float* ln_cg = (const float*)d_in[22];
    const float* ln_cb = (const float*)d_in[23];
    float* out = (float*)d_out;

    void *pKey, *pBase, *pW2, *pC2, *pU, *pR, *pSel, *pX;
    cudaGetSymbolAddress(&pKey, g_key);
    cudaGetSymbolAddress(&pBase, g_base);
    cudaGetSymbolAddress(&pW2, g_W2);
    cudaGetSymbolAddress(&pC2, g_c2);
    cudaGetSymbolAddress(&pU, g_u);
    cudaGetSymbolAddress(&pR, g_R);
    cudaGetSymbolAddress(&pSel, g_selemb);
    cudaGetSymbolAddress(&pX, g_x);

    // preamble (independent)
    k_removed<<<BSZ, 256>>>(sel);
    k_c2<<<1, 256>>>(e2b, q1w);
    // base = ar@q1+q1b -> g_base, relu -> g_R rows [0,512)
    k_gemm<64, 64, 4, 3><<<dim3(BSZ / 64, DF / 64), 256>>>(
        ar, q1w, q1b, (float*)pBase, DIN, DF, nullptr, nullptr, nullptr, (float*)pR);
    // W2 = e2@q1
    k_gemm<32, 64, 2, 0><<<dim3(DF / 32, DF / 64), 256>>>(
        e2w, q1w, nullptr, (float*)pW2, DIN, DF, nullptr, nullptr, nullptr, nullptr);
    // key GEMM + end scatter
    k_gemm<128, 32, 4, 2><<<dim3(BSZ * ENT / 128, 1), 256>>>(
        ent, key_w, key_b, (float*)pKey, DF, DK, endv, nullptr, entity_num, nullptr);
    // pooled embeddings (needs key + removed)
    k_emb<<<BSZ / 8, 256>>>(sel, entity_num, selnum);
    // u = relu(selemb@e1 + e1b)
    k_gemm<64, 64, 4, 5><<<dim3((SEQN - 1) * BSZ / 64, DF / 64), 256>>>(
        (const float*)pSel, e1w, e1b, (float*)pU, DK, DF, nullptr, nullptr, nullptr, nullptr);
    // P = u@W2; epilogue: relu(P + base + c2) -> g_R rows [512, 64*512)
    k_gemm<64, 64, 4, 4><<<dim3((SEQN - 1) * BSZ / 64, DF / 64), 256>>>(
        (const float*)pU, (const float*)pW2, nullptr, nullptr, DF, DF,
        (const float*)pBase, (const float*)pC2, nullptr, (float*)pR);
    // x = g_R @ q2 + q2b
    k_gemm<128, 32, 4, 1><<<dim3(SEQN * BSZ / 128, 1), 256>>>(
        (const float*)pR, q2w, q2b, (float*)pX, DF, DK, nullptr, nullptr, nullptr, nullptr);
    // gx, lstm, logits
    k_gx<<<SEQN * BSZ / 8, 256>>>(wih, ln_ig, ln_ib);
    k_lstm<<<BSZ / 8, 256>>>(whh, ln_hg, ln_hb, ln_cg, ln_cb);
    k_logits<<<BSZ, 256>>>(entity_num, out);
    (void)in_sizes;
    (void)n_in;
    (void)out_size;
}

// round 5
// speedup vs baseline: 1.1971x; 1.0809x over previous
#include <cuda_runtime.h>
#include <math.h>
#include <stdint.h>

#define BSZ 512
#define ENT 512
#define SEQN 64
#define DK 32
#define DF 256
#define DIN 1024
#define NGATE 128
#define ENP1 513
#define BKK 32

typedef unsigned long long u64;

// ----------------------------- static scratch --------------------------------
__device__ float g_key[(size_t)BSZ * ENT * DK];
__device__ int   g_removed[(size_t)BSZ * ENP1];
__device__ float g_selemb[(size_t)SEQN * BSZ * DK];
__device__ float g_base[(size_t)BSZ * DF];
__device__ float g_W2[(size_t)DF * DF];
__device__ float g_c2[DF];
__device__ float g_u[(size_t)(SEQN - 1) * BSZ * DF];
__device__ float g_R[(size_t)SEQN * BSZ * DF];
__device__ float g_gx[(size_t)SEQN * BSZ * NGATE];
__device__ float g_q[(size_t)SEQN * BSZ * DK];

// ----------------------------- helpers ---------------------------------------
__device__ __forceinline__ float wredsum(float v) {
#pragma unroll
    for (int o = 16; o; o >>= 1) v += __shfl_xor_sync(0xffffffffu, v, o);
    return v;
}
__device__ __forceinline__ u64 pk2(float x) {
    u64 r;
    asm("mov.b64 %0,{%1,%1};" : "=l"(r) : "f"(x));
    return r;
}
__device__ __forceinline__ void fma2(u64& d, u64 a, u64 b) {
    asm("fma.rn.f32x2 %0,%1,%2,%0;" : "+l"(d) : "l"(a), "l"(b));
}
__device__ __forceinline__ float2 up2(u64 v) {
    float2 f;
    asm("mov.b64 {%0,%1},%2;" : "=f"(f.x), "=f"(f.y) : "l"(v));
    return f;
}

// --------------- double-buffered FFMA2 GEMM: C[M,N]=A[M,K]@B[K,N] -------------
// EPI: 0 plain | 1 +bias | 2 +bias & end-scatter (key) | 3 +bias->C, relu->C2
//      4 +xb[b]+xc, relu -> C2 at row+BSZ | 5 relu(+bias)
template <int TM, int TN, int RM, int EPI>
__global__ void k_gemm(const float* __restrict__ A, const float* __restrict__ B,
                       const float* __restrict__ bias, float* __restrict__ C,
                       int K, int N,
                       const float* __restrict__ xb, const float* __restrict__ xc,
                       const int* __restrict__ xi, float* __restrict__ C2) {
    __shared__ float As[2][BKK * TM];
    __shared__ float Bs[2][BKK * TN];
    const int t = threadIdx.x;
    constexpr int NT4 = TN / 4;
    const int tx = t % NT4;
    const int ty = t / NT4;
    const int m0 = blockIdx.x * TM;
    const int n0 = blockIdx.y * TN;

    auto loadA = [&](int buf, int k0) {
        constexpr int ALOADS = TM * BKK / 4;
#pragma unroll
        for (int idx = t; idx < ALOADS; idx += 256) {
            int r = idx >> 3;
            int kk = (idx & 7) * 4;
            float4 a = *(const float4*)&A[(size_t)(m0 + r) * K + k0 + kk];
            As[buf][(kk + 0) * TM + r] = a.x;
            As[buf][(kk + 1) * TM + r] = a.y;
            As[buf][(kk + 2) * TM + r] = a.z;
            As[buf][(kk + 3) * TM + r] = a.w;
        }
    };
    auto loadB = [&](int buf, int k0) {
        constexpr int BLOADS = TN * BKK / 4;
#pragma unroll
        for (int idx = t; idx < BLOADS; idx += 256) {
            int kr = idx / NT4;
            int nn = (idx % NT4) * 4;
            *(float4*)&Bs[buf][kr * TN + nn] =
                *(const float4*)&B[(size_t)(k0 + kr) * N + n0 + nn];
        }
    };

    u64 acc[RM][2];
#pragma unroll
    for (int r = 0; r < RM; r++) {
        acc[r][0] = 0ull;
        acc[r][1] = 0ull;
    }

    loadA(0, 0);
    loadB(0, 0);
    __syncthreads();
    const int nIter = K / BKK;
    for (int it = 0; it < nIter; it++) {
        int cur = it & 1, nxt = cur ^ 1;
        if (it + 1 < nIter) {
            loadA(nxt, (it + 1) * BKK);
            loadB(nxt, (it + 1) * BKK);
        }
#pragma unroll
        for (int k = 0; k < BKK; k++) {
            u64 ap[RM];
            if (RM == 4) {
                float4 av = *(const float4*)&As[cur][k * TM + ty * 4];
                ap[0] = pk2(av.x);
                ap[1] = pk2(av.y);
                ap[2] = pk2(av.z);
                ap[3] = pk2(av.w);
            } else {
                float2 av = *(const float2*)&As[cur][k * TM + ty * 2];
                ap[0] = pk2(av.x);
                ap[1] = pk2(av.y);
            }
            ulonglong2 bv = *(const ulonglong2*)&Bs[cur][k * TN + tx * 4];
#pragma unroll
            for (int r = 0; r < RM; r++) {
                fma2(acc[r][0], ap[r], bv.x);
                fma2(acc[r][1], ap[r], bv.y);
            }
        }
        __syncthreads();
    }

    float bb[4] = {0.f, 0.f, 0.f, 0.f};
    if (EPI == 1 || EPI == 2 || EPI == 3 || EPI == 5) {
        float4 b4 = *(const float4*)&bias[n0 + tx * 4];
        bb[0] = b4.x;
        bb[1] = b4.y;
        bb[2] = b4.z;
        bb[3] = b4.w;
    }
#pragma unroll
    for (int r = 0; r < RM; r++) {
        int m = m0 + ty * RM + r;
        int c0 = n0 + tx * 4;
        float2 lo = up2(acc[r][0]);
        float2 hi = up2(acc[r][1]);
        float v[4] = {lo.x, lo.y, hi.x, hi.y};
        if (EPI == 0) {
            *(float4*)&C[(size_t)m * N + c0] = make_float4(v[0], v[1], v[2], v[3]);
        } else if (EPI == 1) {
            *(float4*)&C[(size_t)m * N + c0] =
                make_float4(v[0] + bb[0], v[1] + bb[1], v[2] + bb[2], v[3] + bb[3]);
        } else if (EPI == 2) {
            int en = xi[m >> 9];
            float4 o;
            if ((m & 511) == en) {
                o = *(const float4*)&xb[c0];
            } else {
                o = make_float4(v[0] + bb[0], v[1] + bb[1], v[2] + bb[2], v[3] + bb[3]);
            }
            *(float4*)&C[(size_t)m * N + c0] = o;
        } else if (EPI == 3) {
            float4 o = make_float4(v[0] + bb[0], v[1] + bb[1], v[2] + bb[2], v[3] + bb[3]);
            *(float4*)&C[(size_t)m * N + c0] = o;
            *(float4*)&C2[(size_t)m * N + c0] =
                make_float4(fmaxf(o.x, 0.f), fmaxf(o.y, 0.f), fmaxf(o.z, 0.f), fmaxf(o.w, 0.f));
        } else if (EPI == 4) {
            int b = m & 511;
            float4 bs = *(const float4*)&xb[(size_t)b * N + c0];
            float4 cc = *(const float4*)&xc[c0];
            *(float4*)&C2[(size_t)(m + BSZ) * N + c0] =
                make_float4(fmaxf(v[0] + bs.x + cc.x, 0.f), fmaxf(v[1] + bs.y + cc.y, 0.f),
                            fmaxf(v[2] + bs.z + cc.z, 0.f), fmaxf(v[3] + bs.w + cc.w, 0.f));
        } else if (EPI == 5) {
            *(float4*)&C[(size_t)m * N + c0] =
                make_float4(fmaxf(v[0] + bb[0], 0.f), fmaxf(v[1] + bb[1], 0.f),
                            fmaxf(v[2] + bb[2], 0.f), fmaxf(v[3] + bb[3], 0.f));
        }
    }
}

// --------------- fused x = R@q2+q2b  and  gx = LN(x@wih)*g+b -------------------
__global__ void k_xgx(const float* __restrict__ A, const float* __restrict__ B,
                      const float* __restrict__ q2b, const float* __restrict__ wih,
                      const float* __restrict__ ln_ig, const float* __restrict__ ln_ib) {
    // flat smem: As(2x4096) | Bs(2x1024); epilogue reuse: xsh = sm[0..4223], wsh = sm[4352..8447]
    __shared__ float sm[10240];
    float (*As)[4096] = (float (*)[4096])sm;
    float (*Bs)[1024] = (float (*)[1024])(sm + 8192);
    const int t = threadIdx.x;
    const int tx = t & 7;      // NT4 = 8
    const int ty = t >> 3;     // 0..31
    const int m0 = blockIdx.x * 128;

    auto loadA = [&](int buf, int k0) {
#pragma unroll
        for (int idx = t; idx < 1024; idx += 256) {
            int r = idx >> 3;
            int kk = (idx & 7) * 4;
            float4 a = *(const float4*)&A[(size_t)(m0 + r) * DF + k0 + kk];
            As[buf][(kk + 0) * 128 + r] = a.x;
            As[buf][(kk + 1) * 128 + r] = a.y;
            As[buf][(kk + 2) * 128 + r] = a.z;
            As[buf][(kk + 3) * 128 + r] = a.w;
        }
    };
    auto loadB = [&](int buf, int k0) {
        {
            int kr = t >> 3;
            int nn = (t & 7) * 4;
            *(float4*)&Bs[buf][kr * 32 + nn] = *(const float4*)&B[(size_t)(k0 + kr) * 32 + nn];
        }
    };

    u64 acc[4][2];
#pragma unroll
    for (int r = 0; r < 4; r++) {
        acc[r][0] = 0ull;
        acc[r][1] = 0ull;
    }
    loadA(0, 0);
    loadB(0, 0);
    __syncthreads();
    for (int it = 0; it < DF / BKK; it++) {
        int cur = it & 1, nxt = cur ^ 1;
        if (it + 1 < DF / BKK) {
            loadA(nxt, (it + 1) * BKK);
            loadB(nxt, (it + 1) * BKK);
        }
#pragma unroll
        for (int k = 0; k < BKK; k++) {
            float4 av = *(const float4*)&As[cur][k * 128 + ty * 4];
            u64 ap0 = pk2(av.x), ap1 = pk2(av.y), ap2 = pk2(av.z), ap3 = pk2(av.w);
            ulonglong2 bv = *(const ulonglong2*)&Bs[cur][k * 32 + tx * 4];
            fma2(acc[0][0], ap0, bv.x);
            fma2(acc[0][1], ap0, bv.y);
            fma2(acc[1][0], ap1, bv.x);
            fma2(acc[1][1], ap1, bv.y);
            fma2(acc[2][0], ap2, bv.x);
            fma2(acc[2][1], ap2, bv.y);
            fma2(acc[3][0], ap3, bv.x);
            fma2(acc[3][1], ap3, bv.y);
        }
        __syncthreads();
    }
    // write x (+q2b) into xsh = sm[0..4223] (stride 33); load wih into sm[4352..]
    float* xsh = sm;
    float* wsh = sm + 4352;
    {
        float4 b4 = *(const float4*)&q2b[tx * 4];
        float qb[4] = {b4.x, b4.y, b4.z, b4.w};
#pragma unroll
        for (int r = 0; r < 4; r++) {
            float2 lo = up2(acc[r][0]);
            float2 hi = up2(acc[r][1]);
            int row = ty * 4 + r;
            xsh[row * 33 + tx * 4 + 0] = lo.x + qb[0];
            xsh[row * 33 + tx * 4 + 1] = lo.y + qb[1];
            xsh[row * 33 + tx * 4 + 2] = hi.x + qb[2];
            xsh[row * 33 + tx * 4 + 3] = hi.y + qb[3];
        }
    }
#pragma unroll
    for (int idx = t; idx < 4096; idx += 256) wsh[idx] = wih[idx];
    __syncthreads();

    int lane = t & 31, w = t >> 5;
    float lg[4], lb[4];
#pragma unroll
    for (int g = 0; g < 4; g++) {
        lg[g] = ln_ig[g * 32 + lane];
        lb[g] = ln_ib[g * 32 + lane];
    }
    for (int rr = 0; rr < 16; rr++) {
        int row = rr * 8 + w;
        float xv = xsh[row * 33 + lane];
        float acg[4] = {0.f, 0.f, 0.f, 0.f};
#pragma unroll
        for (int k = 0; k < 32; k++) {
            float xk = __shfl_sync(0xffffffffu, xv, k);
#pragma unroll
            for (int g = 0; g < 4; g++) acg[g] += xk * wsh[k * 128 + g * 32 + lane];
        }
        float s = acg[0] + acg[1] + acg[2] + acg[3];
        float m = wredsum(s) * (1.f / 128.f);
        float vs = 0.f;
#pragma unroll
        for (int g = 0; g < 4; g++) {
            float d = acg[g] - m;
            vs += d * d;
        }
        float v = wredsum(vs) * (1.f / 128.f);
        float rs = rsqrtf(v + 1e-5f);
#pragma unroll
        for (int g = 0; g < 4; g++)
            g_gx[(size_t)(m0 + row) * 128 + g * 32 + lane] = (acg[g] - m) * rs * lg[g] + lb[g];
    }
}

// ------------------- first-removal-step scatter --------------------------------
__global__ void k_removed(const int* __restrict__ sel) {
    int b = blockIdx.x;
    for (int n = threadIdx.x; n < ENP1; n += blockDim.x) g_removed[(size_t)b * ENP1 + n] = 65;
    __syncthreads();
    if (threadIdx.x < SEQN) {
        int s = sel[b * SEQN + threadIdx.x];
        atomicMin(&g_removed[(size_t)b * ENP1 + s], threadIdx.x + 1);
    }
}

// ------------------- per-step pooled embedding (pipelined, warp/batch) ---------
__global__ void k_emb(const int* __restrict__ sel, const int* __restrict__ en_arr,
                      const int* __restrict__ selnum) {
    int t = threadIdx.x;
    int lane = t & 31;
    int b = blockIdx.x * 8 + (t >> 5);
    int en = en_arr[b];
    int sn = selnum[b];
    int s0 = sel[b * SEQN + lane];
    int s1 = sel[b * SEQN + 32 + lane];
    int sc = __shfl_sync(0xffffffffu, s0, 0);
    float kv_n = g_key[((size_t)b * ENT + sc) * DK + lane];
    int rm_n = g_removed[(size_t)b * ENP1 + sc];
    float sum = 0.f;
    int cnt = 0;
    bool endf = false;
    for (int j = 0; j < SEQN; j++) {
        float kv = kv_n;
        int rm = rm_n;
        int s = (j < 32) ? __shfl_sync(0xffffffffu, s0, j) : __shfl_sync(0xffffffffu, s1, j - 32);
        if (j + 1 < SEQN) {
            int s2 = (j + 1 < 32) ? __shfl_sync(0xffffffffu, s0, j + 1)
                                  : __shfl_sync(0xffffffffu, s1, j - 31);
            kv_n = g_key[((size_t)b * ENT + s2) * DK + lane];
            rm_n = g_removed[(size_t)b * ENP1 + s2];
        }
        endf = endf || (s == en);
        if ((!endf) && rm == j + 1) {
            sum += kv;
            cnt++;
        }
        float denom = (sn != 0 && cnt > 0) ? (float)cnt : 1.f;
        g_selemb[((size_t)j * BSZ + b) * DK + lane] = sum / denom;
    }
}

// ------------------- c2 = e2_b @ q1_w ------------------------------------------
__global__ void k_c2(const float* __restrict__ e2b, const float* __restrict__ q1w) {
    int t = threadIdx.x;
    float acc = 0.f;
    for (int k = 0; k < DIN; k++) acc += e2b[k] * q1w[(size_t)k * DF + t];
    g_c2[t] = acc;
}

// ------------------- sequential LN-LSTM (warp/batch, gx prefetched) ------------
__global__ void k_lstm(const float* __restrict__ whh, const float* __restrict__ ln_hg,
                       const float* __restrict__ ln_hb, const float* __restrict__ ln_cg,
                       const float* __restrict__ ln_cb) {
    __shared__ float wsh[32 * 128];
    int t = threadIdx.x;
    for (int idx = t; idx < 4096; idx += 256) wsh[idx] = whh[idx];
    __syncthreads();
    int lane = t & 31, w = t >> 5;
    int b = blockIdx.x * 8 + w;
    float h = 0.f, c = 0.f;
    float hg[4], hb[4];
#pragma unroll
    for (int g = 0; g < 4; g++) {
        int cc = g * 32 + lane;
        hg[g] = ln_hg[cc];
        hb[g] = ln_hb[cc];
    }
    float cgm = ln_cg[lane], cbm = ln_cb[lane];
    float gxr[4];
#pragma unroll
    for (int g = 0; g < 4; g++) gxr[g] = g_gx[(size_t)b * 128 + g * 32 + lane];
    for (int i = 0; i < SEQN; i++) {
        float gxn[4];
        if (i + 1 < SEQN) {
            size_t rn = (size_t)(i + 1) * BSZ + b;
#pragma unroll
            for (int g = 0; g < 4; g++) gxn[g] = g_gx[rn * 128 + g * 32 + lane];
        }
        float acc[4] = {0.f, 0.f, 0.f, 0.f};
#pragma unroll
        for (int k = 0; k < 32; k++) {
            float hk = __shfl_sync(0xffffffffu, h, k);
#pragma unroll
            for (int g = 0; g < 4; g++) acc[g] += hk * wsh[k * 128 + g * 32 + lane];
        }
        float s = acc[0] + acc[1] + acc[2] + acc[3];
        float m = wredsum(s) * (1.f / 128.f);
        float vs = 0.f;
#pragma unroll
        for (int g = 0; g < 4; g++) {
            float d = acc[g] - m;
            vs += d * d;
        }
        float v = wredsum(vs) * (1.f / 128.f);
        float rs = rsqrtf(v + 1e-5f);
        float gate[4];
#pragma unroll
        for (int g = 0; g < 4; g++) gate[g] = gxr[g] + (acc[g] - m) * rs * hg[g] + hb[g];
        float ii = 1.f / (1.f + __expf(-gate[0]));
        float ff = 1.f / (1.f + __expf(-gate[1]));
        float gg = tanhf(gate[2]);
        float oo = 1.f / (1.f + __expf(-gate[3]));
        float cn = ff * c + ii * gg;
        float mc = wredsum(cn) * (1.f / 32.f);
        float dc = cn - mc;
        float vc = wredsum(dc * dc) * (1.f / 32.f);
        c = dc * rsqrtf(vc + 1e-5f) * cgm + cbm;
        h = oo * tanhf(c);
        g_q[((size_t)i * BSZ + b) * DK + lane] = h;
#pragma unroll
        for (int g = 0; g < 4; g++) gxr[g] = gxn[g];
    }
}

// ------------------- logits + mask ---------------------------------------------
__global__ void k_logits(const int* __restrict__ en_arr, float* __restrict__ out) {
    __shared__ float Qsh[64 * 32];
    __shared__ float Ksh[256 * 34];
    __shared__ int rsh[256];
    int t = threadIdx.x;
    int b = blockIdx.x;
    int en = en_arr[b];
    for (int idx = t; idx < 2048; idx += 256) {
        int s = idx >> 5, k = idx & 31;
        Qsh[idx] = g_q[((size_t)s * BSZ + b) * 32 + k];
    }
    const u64* Q2 = (const u64*)Qsh;
    for (int tile = 0; tile < 2; tile++) {
        int n0 = tile * 256;
        __syncthreads();
        for (int idx = t; idx < 8192; idx += 256) {
            int n = idx >> 5, k = idx & 31;
            Ksh[n * 34 + k] = g_key[((size_t)b * ENT + n0 + n) * 32 + k];
        }
        rsh[t] = g_removed[(size_t)b * ENP1 + n0 + t];
        __syncthreads();
        u64 kreg[16];
#pragma unroll
        for (int kp = 0; kp < 16; kp++) {
            float2 kk = *(const float2*)&Ksh[t * 34 + kp * 2];
            asm("mov.b64 %0,{%1,%2};" : "=l"(kreg[kp]) : "f"(kk.x), "f"(kk.y));
        }
        int rstep = rsh[t];
        int n = n0 + t;
        for (int s = 0; s < SEQN; s++) {
            u64 a0 = 0ull, a1 = 0ull;
#pragma unroll
            for (int kp = 0; kp < 16; kp += 2) {
                fma2(a0, kreg[kp], Q2[s * 16 + kp]);
                fma2(a1, kreg[kp + 1], Q2[s * 16 + kp + 1]);
            }
            float2 f0 = up2(a0), f1 = up2(a1);
            float dot = (f0.x + f0.y) + (f1.x + f1.y);
            bool keep = (n < en) ? (rstep > s) : ((n == en) ? (s >= 1 && rstep > s) : false);
            out[((size_t)b * SEQN + s) * ENP1 + n] = keep ? dot : -1e9f;
        }
    }
    if (t < SEQN) out[((size_t)b * SEQN + t) * ENP1 + 512] = -1e9f;
}

// ------------------------------- launch ----------------------------------------
extern "C" void kernel_launch(void* const* d_in, const int* in_sizes, int n_in,
                              void* d_out, int out_size) {
    const float* ent = (const float*)d_in[0];
    const float* ar = (const float*)d_in[1];
    const int* entity_num = (const int*)d_in[2];
    const int* sel = (const int*)d_in[3];
    const int* selnum = (const int*)d_in[4];
    const float* key_w = (const float*)d_in[5];
    const float* key_b = (const float*)d_in[6];
    const float* q1w = (const float*)d_in[7];
    const float* q1b = (const float*)d_in[8];
    const float* q2w = (const float*)d_in[9];
    const float* q2b = (const float*)d_in[10];
    const float* e1w = (const float*)d_in[11];
    const float* e1b = (const float*)d_in[12];
    const float* e2w = (const float*)d_in[13];
    const float* e2b = (const float*)d_in[14];
    const float* endv = (const float*)d_in[15];
    const float* wih = (const float*)d_in[16];
    const float* whh = (const float*)d_in[17];
    const float* ln_ig = (const float*)d_in[18];
    const float* ln_ib = (const float*)d_in[19];
    const float* ln_hg = (const float*)d_in[20];
    const float* ln_hb = (const float*)d_in[21];
    const float* ln_cg = (const float*)d_in[22];
    const float* ln_cb = (const float*)d_in[23];
    float* out = (float*)d_out;

    void *pKey, *pBase, *pW2, *pC2, *pU, *pR, *pSel;
    cudaGetSymbolAddress(&pKey, g_key);
    cudaGetSymbolAddress(&pBase, g_base);
    cudaGetSymbolAddress(&pW2, g_W2);
    cudaGetSymbolAddress(&pC2, g_c2);
    cudaGetSymbolAddress(&pU, g_u);
    cudaGetSymbolAddress(&pR, g_R);
    cudaGetSymbolAddress(&pSel, g_selemb);

    static cudaStream_t sA = 0, sB = 0;
    static cudaEvent_t eFork = 0, eRm = 0, ePre = 0;
    if (!sA) {
        cudaStreamCreateWithFlags(&sA, cudaStreamNonBlocking);
        cudaStreamCreateWithFlags(&sB, cudaStreamNonBlocking);
        cudaEventCreateWithFlags(&eFork, cudaEventDisableTiming);
        cudaEventCreateWithFlags(&eRm, cudaEventDisableTiming);
        cudaEventCreateWithFlags(&ePre, cudaEventDisableTiming);
    }

    // fork
    cudaEventRecord(eFork, 0);
    cudaStreamWaitEvent(sA, eFork, 0);
    cudaStreamWaitEvent(sB, eFork, 0);

    // side stream A: removal scatter
    k_removed<<<BSZ, 256, 0, sA>>>(sel);
    cudaEventRecord(eRm, sA);

    // side stream B: c2, base (+relu->R[0:512)), W2
    k_c2<<<1, 256, 0, sB>>>(e2b, q1w);
    k_gemm<64, 64, 4, 3><<<dim3(BSZ / 64, DF / 64), 256, 0, sB>>>(
        ar, q1w, q1b, (float*)pBase, DIN, DF, nullptr, nullptr, nullptr, (float*)pR);
    k_gemm<64, 64, 4, 0><<<dim3(DF / 64, DF / 64), 256, 0, sB>>>(
        e2w, q1w, nullptr, (float*)pW2, DIN, DF, nullptr, nullptr, nullptr, nullptr);
    cudaEventRecord(ePre, sB);

    // main stream: key GEMM (big) overlaps side streams
    k_gemm<128, 32, 4, 2><<<dim3(BSZ * ENT / 128, 1), 256>>>(
        ent, key_w, key_b, (float*)pKey, DF, DK, endv, nullptr, entity_num, nullptr);

    // emb needs key + removed
    cudaStreamWaitEvent(0, eRm, 0);
    k_emb<<<BSZ / 8, 256>>>(sel, entity_num, selnum);
    // u = relu(selemb@e1 + e1b)
    k_gemm<64, 64, 4, 5><<<dim3((SEQN - 1) * BSZ / 64, DF / 64), 256>>>(
        (const float*)pSel, e1w, e1b, (float*)pU, DK, DF, nullptr, nullptr, nullptr, nullptr);
    // P = u@W2 + base + c2, relu -> g_R rows [512, 32768)
    cudaStreamWaitEvent(0, ePre, 0);
    k_gemm<64, 64, 4, 4><<<dim3((SEQN - 1) * BSZ / 64, DF / 64), 256>>>(
        (const float*)pU, (const float*)pW2, nullptr, nullptr, DF, DF,
        (const float*)pBase, (const float*)pC2, nullptr, (float*)pR);
    // fused x GEMM + gates LN
    k_xgx<<<SEQN * BSZ / 128, 256>>>((const float*)pR, q2w, q2b, wih, ln_ig, ln_ib);
    // lstm + logits
    k_lstm<<<BSZ / 8, 256>>>(whh, ln_hg, ln_hb, ln_cg, ln_cb);
    k_logits<<<BSZ, 256>>>(entity_num, out);
    (void)in_sizes;
    (void)n_in;
    (void)out_size;
}

// round 6
// speedup vs baseline: 1.7234x; 1.4397x over previous
#include <cuda_runtime.h>
#include <math.h>
#include <stdint.h>

#define BSZ 512
#define ENT 512
#define SEQN 64
#define DK 32
#define DF 256
#define DIN 1024
#define NGATE 128
#define ENP1 513

typedef unsigned long long u64;

// ----------------------------- static scratch --------------------------------
__device__ float g_key[(size_t)BSZ * ENT * DK];
__device__ int   g_removed[(size_t)BSZ * ENP1];
__device__ float g_selemb[(size_t)SEQN * BSZ * DK];
__device__ float g_base[(size_t)BSZ * DF];
__device__ float g_W2[(size_t)DF * DF];
__device__ float g_c2[DF];
__device__ float g_u[(size_t)(SEQN - 1) * BSZ * DF];
__device__ float g_R[(size_t)SEQN * BSZ * DF];
__device__ float g_gx[(size_t)SEQN * BSZ * NGATE];
__device__ float g_q[(size_t)SEQN * BSZ * DK];

// ----------------------------- helpers ---------------------------------------
__device__ __forceinline__ float wredsum(float v) {
#pragma unroll
    for (int o = 16; o; o >>= 1) v += __shfl_xor_sync(0xffffffffu, v, o);
    return v;
}
__device__ __forceinline__ u64 pk2(float x) {
    u64 r;
    asm("mov.b64 %0,{%1,%1};" : "=l"(r) : "f"(x));
    return r;
}
__device__ __forceinline__ void fma2(u64& d, u64 a, u64 b) {
    asm("fma.rn.f32x2 %0,%1,%2,%0;" : "+l"(d) : "l"(a), "l"(b));
}
__device__ __forceinline__ float2 up2(u64 v) {
    float2 f;
    asm("mov.b64 {%0,%1},%2;" : "=f"(f.x), "=f"(f.y) : "l"(v));
    return f;
}
__device__ __forceinline__ uint32_t f2tf(float f) {
    uint32_t r;
    asm("cvt.rna.tf32.f32 %0, %1;" : "=r"(r) : "f"(f));
    return r;
}
__device__ __forceinline__ void mma_tf32(float* c, uint32_t a0, uint32_t a1, uint32_t a2,
                                         uint32_t a3, uint32_t b0, uint32_t b1) {
    asm volatile(
        "mma.sync.aligned.m16n8k8.row.col.f32.tf32.tf32.f32 "
        "{%0,%1,%2,%3},{%4,%5,%6,%7},{%8,%9},{%0,%1,%2,%3};"
        : "+f"(c[0]), "+f"(c[1]), "+f"(c[2]), "+f"(c[3])
        : "r"(a0), "r"(a1), "r"(a2), "r"(a3), "r"(b0), "r"(b1));
}

// --------------- tf32 tensor-core GEMM: C[M,N]=A[M,K]@B[K,N] ------------------
// BM=64, 8 warps (4 M x 2 N), warp tile 16 x (BN/2), KC=32 chunks.
// EPI: 0 plain | 2 +bias & end-scatter (key) | 3 +bias->C, relu->C2 (base)
//      4 +xb[b]+xc, relu -> C2 at row+BSZ (P) | 5 relu(+bias) (u)
template <int BN, int EPI>
__global__ void k_mma(const float* __restrict__ A, const float* __restrict__ B,
                      const float* __restrict__ bias, float* __restrict__ C,
                      int K, int N,
                      const float* __restrict__ xb, const float* __restrict__ xc,
                      const int* __restrict__ xi, float* __restrict__ C2) {
    constexpr int BM = 64, KC = 32;
    constexpr int NBLD = (KC * BN) / 1024;  // float4 B loads per thread (1 or 2)
    constexpr int NT = BN / 16;             // n8 tiles per warp
    __shared__ uint32_t As[BM][KC + 4];
    __shared__ uint32_t Bs[KC][BN + 4];
    const int t = threadIdx.x;
    const int wid = t >> 5, lane = t & 31;
    const int gid = lane >> 2, tig = lane & 3;
    const int warpM = wid & 3, warpN = wid >> 2;
    const int m0 = blockIdx.x * BM;
    const int n0 = blockIdx.y * BN;

    float cr[NT][4];
#pragma unroll
    for (int j = 0; j < NT; j++) {
        cr[j][0] = 0.f; cr[j][1] = 0.f; cr[j][2] = 0.f; cr[j][3] = 0.f;
    }

    const int ar0 = t >> 3;          // 0..31 (and +32)
    const int ak = (t & 7) * 4;
    constexpr int BQ = BN / 4;
    const int br0 = t / BQ;
    const int bn = (t % BQ) * 4;

    float4 pa0, pa1, pb[NBLD];
    pa0 = *(const float4*)&A[(size_t)(m0 + ar0) * K + ak];
    pa1 = *(const float4*)&A[(size_t)(m0 + ar0 + 32) * K + ak];
#pragma unroll
    for (int i = 0; i < NBLD; i++) {
        int kr = br0 + i * (256 / BQ);
        pb[i] = *(const float4*)&B[(size_t)kr * N + n0 + bn];
    }

    const int nch = K / KC;
    for (int ch = 0; ch < nch; ch++) {
        __syncthreads();
        {
            uint4 q;
            q.x = f2tf(pa0.x); q.y = f2tf(pa0.y); q.z = f2tf(pa0.z); q.w = f2tf(pa0.w);
            *(uint4*)&As[ar0][ak] = q;
            q.x = f2tf(pa1.x); q.y = f2tf(pa1.y); q.z = f2tf(pa1.z); q.w = f2tf(pa1.w);
            *(uint4*)&As[ar0 + 32][ak] = q;
#pragma unroll
            for (int i = 0; i < NBLD; i++) {
                int kr = br0 + i * (256 / BQ);
                q.x = f2tf(pb[i].x); q.y = f2tf(pb[i].y);
                q.z = f2tf(pb[i].z); q.w = f2tf(pb[i].w);
                *(uint4*)&Bs[kr][bn] = q;
            }
        }
        if (ch + 1 < nch) {
            int k0 = (ch + 1) * KC;
            pa0 = *(const float4*)&A[(size_t)(m0 + ar0) * K + k0 + ak];
            pa1 = *(const float4*)&A[(size_t)(m0 + ar0 + 32) * K + k0 + ak];
#pragma unroll
            for (int i = 0; i < NBLD; i++) {
                int kr = k0 + br0 + i * (256 / BQ);
                pb[i] = *(const float4*)&B[(size_t)kr * N + n0 + bn];
            }
        }
        __syncthreads();
#pragma unroll
        for (int kk = 0; kk < KC; kk += 8) {
            uint32_t a0 = As[warpM * 16 + gid][kk + tig];
            uint32_t a1 = As[warpM * 16 + gid + 8][kk + tig];
            uint32_t a2 = As[warpM * 16 + gid][kk + tig + 4];
            uint32_t a3 = As[warpM * 16 + gid + 8][kk + tig + 4];
#pragma unroll
            for (int j = 0; j < NT; j++) {
                int nb = warpN * (BN / 2) + j * 8;
                uint32_t b0 = Bs[kk + tig][nb + gid];
                uint32_t b1 = Bs[kk + tig + 4][nb + gid];
                mma_tf32(cr[j], a0, a1, a2, a3, b0, b1);
            }
        }
    }

    // epilogue
    const int rb = m0 + warpM * 16 + gid;
#pragma unroll
    for (int j = 0; j < NT; j++) {
        int cb = n0 + warpN * (BN / 2) + j * 8 + tig * 2;
#pragma unroll
        for (int h = 0; h < 2; h++) {
            int m = rb + h * 8;
            float v0 = cr[j][h * 2 + 0];
            float v1 = cr[j][h * 2 + 1];
            if (EPI == 0) {
                C[(size_t)m * N + cb] = v0;
                C[(size_t)m * N + cb + 1] = v1;
            } else if (EPI == 2) {
                int en = xi[m0 >> 9];
                if ((m & 511) == en) {
                    C[(size_t)m * N + cb] = xb[cb];
                    C[(size_t)m * N + cb + 1] = xb[cb + 1];
                } else {
                    C[(size_t)m * N + cb] = v0 + bias[cb];
                    C[(size_t)m * N + cb + 1] = v1 + bias[cb + 1];
                }
            } else if (EPI == 3) {
                float o0 = v0 + bias[cb], o1 = v1 + bias[cb + 1];
                C[(size_t)m * N + cb] = o0;
                C[(size_t)m * N + cb + 1] = o1;
                C2[(size_t)m * N + cb] = fmaxf(o0, 0.f);
                C2[(size_t)m * N + cb + 1] = fmaxf(o1, 0.f);
            } else if (EPI == 4) {
                int b = m & 511;
                float o0 = v0 + xb[(size_t)b * N + cb] + xc[cb];
                float o1 = v1 + xb[(size_t)b * N + cb + 1] + xc[cb + 1];
                C2[(size_t)(m + BSZ) * N + cb] = fmaxf(o0, 0.f);
                C2[(size_t)(m + BSZ) * N + cb + 1] = fmaxf(o1, 0.f);
            } else if (EPI == 5) {
                C[(size_t)m * N + cb] = fmaxf(v0 + bias[cb], 0.f);
                C[(size_t)m * N + cb + 1] = fmaxf(v1 + bias[cb + 1], 0.f);
            }
        }
    }
}

// --------------- fused x = R@q2+q2b  and  gx = LN(x@wih)*g+b -------------------
__global__ void k_xgx(const float* __restrict__ A, const float* __restrict__ B,
                      const float* __restrict__ q2b, const float* __restrict__ wih,
                      const float* __restrict__ ln_ig, const float* __restrict__ ln_ib) {
    __shared__ float sm[10240];
    float (*As)[4096] = (float (*)[4096])sm;
    float (*Bs)[1024] = (float (*)[1024])(sm + 8192);
    const int t = threadIdx.x;
    const int tx = t & 7;
    const int ty = t >> 3;
    const int m0 = blockIdx.x * 128;

    auto loadA = [&](int buf, int k0) {
#pragma unroll
        for (int idx = t; idx < 1024; idx += 256) {
            int r = idx >> 3;
            int kk = (idx & 7) * 4;
            float4 a = *(const float4*)&A[(size_t)(m0 + r) * DF + k0 + kk];
            As[buf][(kk + 0) * 128 + r] = a.x;
            As[buf][(kk + 1) * 128 + r] = a.y;
            As[buf][(kk + 2) * 128 + r] = a.z;
            As[buf][(kk + 3) * 128 + r] = a.w;
        }
    };
    auto loadB = [&](int buf, int k0) {
        int kr = t >> 3;
        int nn = (t & 7) * 4;
        *(float4*)&Bs[buf][kr * 32 + nn] = *(const float4*)&B[(size_t)(k0 + kr) * 32 + nn];
    };

    u64 acc[4][2];
#pragma unroll
    for (int r = 0; r < 4; r++) {
        acc[r][0] = 0ull;
        acc[r][1] = 0ull;
    }
    loadA(0, 0);
    loadB(0, 0);
    __syncthreads();
    for (int it = 0; it < DF / 32; it++) {
        int cur = it & 1, nxt = cur ^ 1;
        if (it + 1 < DF / 32) {
            loadA(nxt, (it + 1) * 32);
            loadB(nxt, (it + 1) * 32);
        }
#pragma unroll
        for (int k = 0; k < 32; k++) {
            float4 av = *(const float4*)&As[cur][k * 128 + ty * 4];
            u64 ap0 = pk2(av.x), ap1 = pk2(av.y), ap2 = pk2(av.z), ap3 = pk2(av.w);
            ulonglong2 bv = *(const ulonglong2*)&Bs[cur][k * 32 + tx * 4];
            fma2(acc[0][0], ap0, bv.x);
            fma2(acc[0][1], ap0, bv.y);
            fma2(acc[1][0], ap1, bv.x);
            fma2(acc[1][1], ap1, bv.y);
            fma2(acc[2][0], ap2, bv.x);
            fma2(acc[2][1], ap2, bv.y);
            fma2(acc[3][0], ap3, bv.x);
            fma2(acc[3][1], ap3, bv.y);
        }
        __syncthreads();
    }
    float* xsh = sm;
    float* wsh = sm + 4352;
    {
        float4 b4 = *(const float4*)&q2b[tx * 4];
        float qb[4] = {b4.x, b4.y, b4.z, b4.w};
#pragma unroll
        for (int r = 0; r < 4; r++) {
            float2 lo = up2(acc[r][0]);
            float2 hi = up2(acc[r][1]);
            int row = ty * 4 + r;
            xsh[row * 33 + tx * 4 + 0] = lo.x + qb[0];
            xsh[row * 33 + tx * 4 + 1] = lo.y + qb[1];
            xsh[row * 33 + tx * 4 + 2] = hi.x + qb[2];
            xsh[row * 33 + tx * 4 + 3] = hi.y + qb[3];
        }
    }
#pragma unroll
    for (int idx = t; idx < 4096; idx += 256) wsh[idx] = wih[idx];
    __syncthreads();

    int lane = t & 31, w = t >> 5;
    float lg[4], lb[4];
#pragma unroll
    for (int g = 0; g < 4; g++) {
        lg[g] = ln_ig[g * 32 + lane];
        lb[g] = ln_ib[g * 32 + lane];
    }
    for (int rr = 0; rr < 16; rr++) {
        int row = rr * 8 + w;
        float xv = xsh[row * 33 + lane];
        float acg[4] = {0.f, 0.f, 0.f, 0.f};
#pragma unroll
        for (int k = 0; k < 32; k++) {
            float xk = __shfl_sync(0xffffffffu, xv, k);
#pragma unroll
            for (int g = 0; g < 4; g++) acg[g] += xk * wsh[k * 128 + g * 32 + lane];
        }
        float s = acg[0] + acg[1] + acg[2] + acg[3];
        float m = wredsum(s) * (1.f / 128.f);
        float vs = 0.f;
#pragma unroll
        for (int g = 0; g < 4; g++) {
            float d = acg[g] - m;
            vs += d * d;
        }
        float v = wredsum(vs) * (1.f / 128.f);
        float rs = rsqrtf(v + 1e-5f);
#pragma unroll
        for (int g = 0; g < 4; g++)
            g_gx[(size_t)(m0 + row) * 128 + g * 32 + lane] = (acg[g] - m) * rs * lg[g] + lb[g];
    }
}

// ------------------- first-removal-step scatter --------------------------------
__global__ void k_removed(const int* __restrict__ sel) {
    int b = blockIdx.x;
    for (int n = threadIdx.x; n < ENP1; n += blockDim.x) g_removed[(size_t)b * ENP1 + n] = 65;
    __syncthreads();
    if (threadIdx.x < SEQN) {
        int s = sel[b * SEQN + threadIdx.x];
        atomicMin(&g_removed[(size_t)b * ENP1 + s], threadIdx.x + 1);
    }
}

// ------------------- per-step pooled embedding (pipelined, warp/batch) ---------
__global__ void k_emb(const int* __restrict__ sel, const int* __restrict__ en_arr,
                      const int* __restrict__ selnum) {
    int t = threadIdx.x;
    int lane = t & 31;
    int b = blockIdx.x * 8 + (t >> 5);
    int en = en_arr[b];
    int sn = selnum[b];
    int s0 = sel[b * SEQN + lane];
    int s1 = sel[b * SEQN + 32 + lane];
    int sc = __shfl_sync(0xffffffffu, s0, 0);
    float kv_n = g_key[((size_t)b * ENT + sc) * DK + lane];
    int rm_n = g_removed[(size_t)b * ENP1 + sc];
    float sum = 0.f;
    int cnt = 0;
    bool endf = false;
    for (int j = 0; j < SEQN; j++) {
        float kv = kv_n;
        int rm = rm_n;
        int s = (j < 32) ? __shfl_sync(0xffffffffu, s0, j) : __shfl_sync(0xffffffffu, s1, j - 32);
        if (j + 1 < SEQN) {
            int s2 = (j + 1 < 32) ? __shfl_sync(0xffffffffu, s0, j + 1)
                                  : __shfl_sync(0xffffffffu, s1, j - 31);
            kv_n = g_key[((size_t)b * ENT + s2) * DK + lane];
            rm_n = g_removed[(size_t)b * ENP1 + s2];
        }
        endf = endf || (s == en);
        if ((!endf) && rm == j + 1) {
            sum += kv;
            cnt++;
        }
        float denom = (sn != 0 && cnt > 0) ? (float)cnt : 1.f;
        g_selemb[((size_t)j * BSZ + b) * DK + lane] = sum / denom;
    }
}

// ------------------- c2 = e2_b @ q1_w ------------------------------------------
__global__ void k_c2(const float* __restrict__ e2b, const float* __restrict__ q1w) {
    int t = threadIdx.x;
    float acc = 0.f;
    for (int k = 0; k < DIN; k++) acc += e2b[k] * q1w[(size_t)k * DF + t];
    g_c2[t] = acc;
}

// ------------------- sequential LN-LSTM (warp/batch, gx prefetched) ------------
__global__ void k_lstm(const float* __restrict__ whh, const float* __restrict__ ln_hg,
                       const float* __restrict__ ln_hb, const float* __restrict__ ln_cg,
                       const float* __restrict__ ln_cb) {
    __shared__ float wsh[32 * 128];
    int t = threadIdx.x;
    for (int idx = t; idx < 4096; idx += 256) wsh[idx] = whh[idx];
    __syncthreads();
    int lane = t & 31, w = t >> 5;
    int b = blockIdx.x * 8 + w;
    float h = 0.f, c = 0.f;
    float hg[4], hb[4];
#pragma unroll
    for (int g = 0; g < 4; g++) {
        int cc = g * 32 + lane;
        hg[g] = ln_hg[cc];
        hb[g] = ln_hb[cc];
    }
    float cgm = ln_cg[lane], cbm = ln_cb[lane];
    float gxr[4];
#pragma unroll
    for (int g = 0; g < 4; g++) gxr[g] = g_gx[(size_t)b * 128 + g * 32 + lane];
    for (int i = 0; i < SEQN; i++) {
        float gxn[4];
        if (i + 1 < SEQN) {
            size_t rn = (size_t)(i + 1) * BSZ + b;
#pragma unroll
            for (int g = 0; g < 4; g++) gxn[g] = g_gx[rn * 128 + g * 32 + lane];
        }
        float acc[4] = {0.f, 0.f, 0.f, 0.f};
#pragma unroll
        for (int k = 0; k < 32; k++) {
            float hk = __shfl_sync(0xffffffffu, h, k);
#pragma unroll
            for (int g = 0; g < 4; g++) acc[g] += hk * wsh[k * 128 + g * 32 + lane];
        }
        float s = acc[0] + acc[1] + acc[2] + acc[3];
        float m = wredsum(s) * (1.f / 128.f);
        float vs = 0.f;
#pragma unroll
        for (int g = 0; g < 4; g++) {
            float d = acc[g] - m;
            vs += d * d;
        }
        float v = wredsum(vs) * (1.f / 128.f);
        float rs = rsqrtf(v + 1e-5f);
        float gate[4];
#pragma unroll
        for (int g = 0; g < 4; g++) gate[g] = gxr[g] + (acc[g] - m) * rs * hg[g] + hb[g];
        float ii = 1.f / (1.f + __expf(-gate[0]));
        float ff = 1.f / (1.f + __expf(-gate[1]));
        float gg = tanhf(gate[2]);
        float oo = 1.f / (1.f + __expf(-gate[3]));
        float cn = ff * c + ii * gg;
        float mc = wredsum(cn) * (1.f / 32.f);
        float dc = cn - mc;
        float vc = wredsum(dc * dc) * (1.f / 32.f);
        c = dc * rsqrtf(vc + 1e-5f) * cgm + cbm;
        h = oo * tanhf(c);
        g_q[((size_t)i * BSZ + b) * DK + lane] = h;
#pragma unroll
        for (int g = 0; g < 4; g++) gxr[g] = gxn[g];
    }
}

// ------------------- logits + mask ---------------------------------------------
__global__ void k_logits(const int* __restrict__ en_arr, float* __restrict__ out) {
    __shared__ float Qsh[64 * 32];
    __shared__ float Ksh[256 * 34];
    __shared__ int rsh[256];
    int t = threadIdx.x;
    int b = blockIdx.x;
    int en = en_arr[b];
    for (int idx = t; idx < 2048; idx += 256) {
        int s = idx >> 5, k = idx & 31;
        Qsh[idx] = g_q[((size_t)s * BSZ + b) * 32 + k];
    }
    const u64* Q2 = (const u64*)Qsh;
    for (int tile = 0; tile < 2; tile++) {
        int n0 = tile * 256;
        __syncthreads();
        for (int idx = t; idx < 8192; idx += 256) {
            int n = idx >> 5, k = idx & 31;
            Ksh[n * 34 + k] = g_key[((size_t)b * ENT + n0 + n) * 32 + k];
        }
        rsh[t] = g_removed[(size_t)b * ENP1 + n0 + t];
        __syncthreads();
        u64 kreg[16];
#pragma unroll
        for (int kp = 0; kp < 16; kp++) {
            float2 kk = *(const float2*)&Ksh[t * 34 + kp * 2];
            asm("mov.b64 %0,{%1,%2};" : "=l"(kreg[kp]) : "f"(kk.x), "f"(kk.y));
        }
        int rstep = rsh[t];
        int n = n0 + t;
        for (int s = 0; s < SEQN; s++) {
            u64 a0 = 0ull, a1 = 0ull;
#pragma unroll
            for (int kp = 0; kp < 16; kp += 2) {
                fma2(a0, kreg[kp], Q2[s * 16 + kp]);
                fma2(a1, kreg[kp + 1], Q2[s * 16 + kp + 1]);
            }
            float2 f0 = up2(a0), f1 = up2(a1);
            float dot = (f0.x + f0.y) + (f1.x + f1.y);
            bool keep = (n < en) ? (rstep > s) : ((n == en) ? (s >= 1 && rstep > s) : false);
            out[((size_t)b * SEQN + s) * ENP1 + n] = keep ? dot : -1e9f;
        }
    }
    if (t < SEQN) out[((size_t)b * SEQN + t) * ENP1 + 512] = -1e9f;
}

// ------------------------------- launch ----------------------------------------
extern "C" void kernel_launch(void* const* d_in, const int* in_sizes, int n_in,
                              void* d_out, int out_size) {
    const float* ent = (const float*)d_in[0];
    const float* ar = (const float*)d_in[1];
    const int* entity_num = (const int*)d_in[2];
    const int* sel = (const int*)d_in[3];
    const int* selnum = (const int*)d_in[4];
    const float* key_w = (const float*)d_in[5];
    const float* key_b = (const float*)d_in[6];
    const float* q1w = (const float*)d_in[7];
    const float* q1b = (const float*)d_in[8];
    const float* q2w = (const float*)d_in[9];
    const float* q2b = (const float*)d_in[10];
    const float* e1w = (const float*)d_in[11];
    const float* e1b = (const float*)d_in[12];
    const float* e2w = (const float*)d_in[13];
    const float* e2b = (const float*)d_in[14];
    const float* endv = (const float*)d_in[15];
    const float* wih = (const float*)d_in[16];
    const float* whh = (const float*)d_in[17];
    const float* ln_ig = (const float*)d_in[18];
    const float* ln_ib = (const float*)d_in[19];
    const float* ln_hg = (const float*)d_in[20];
    const float* ln_hb = (const float*)d_in[21];
    const float* ln_cg = (const float*)d_in[22];
    const float* ln_cb = (const float*)d_in[23];
    float* out = (float*)d_out;

    void *pKey, *pBase, *pW2, *pC2, *pU, *pR, *pSel;
    cudaGetSymbolAddress(&pKey, g_key);
    cudaGetSymbolAddress(&pBase, g_base);
    cudaGetSymbolAddress(&pW2, g_W2);
    cudaGetSymbolAddress(&pC2, g_c2);
    cudaGetSymbolAddress(&pU, g_u);
    cudaGetSymbolAddress(&pR, g_R);
    cudaGetSymbolAddress(&pSel, g_selemb);

    static cudaStream_t sA = 0, sB = 0;
    static cudaEvent_t eFork = 0, eRm = 0, ePre = 0;
    if (!sA) {
        cudaStreamCreateWithFlags(&sA, cudaStreamNonBlocking);
        cudaStreamCreateWithFlags(&sB, cudaStreamNonBlocking);
        cudaEventCreateWithFlags(&eFork, cudaEventDisableTiming);
        cudaEventCreateWithFlags(&eRm, cudaEventDisableTiming);
        cudaEventCreateWithFlags(&ePre, cudaEventDisableTiming);
    }

    // fork
    cudaEventRecord(eFork, 0);
    cudaStreamWaitEvent(sA, eFork, 0);
    cudaStreamWaitEvent(sB, eFork, 0);

    // side stream A: removal scatter
    k_removed<<<BSZ, 256, 0, sA>>>(sel);
    cudaEventRecord(eRm, sA);

    // side stream B: c2, base(+relu->R[0:512)), W2 — all tf32 mma
    k_c2<<<1, 256, 0, sB>>>(e2b, q1w);
    k_mma<64, 3><<<dim3(BSZ / 64, DF / 64), 256, 0, sB>>>(
        ar, q1w, q1b, (float*)pBase, DIN, DF, nullptr, nullptr, nullptr, (float*)pR);
    k_mma<64, 0><<<dim3(DF / 64, DF / 64), 256, 0, sB>>>(
        e2w, q1w, nullptr, (float*)pW2, DIN, DF, nullptr, nullptr, nullptr, nullptr);
    cudaEventRecord(ePre, sB);

    // main stream: key GEMM (tf32 mma, memory-bound) overlaps side streams
    k_mma<32, 2><<<dim3(BSZ * ENT / 64, 1), 256>>>(
        ent, key_w, key_b, (float*)pKey, DF, DK, endv, nullptr, entity_num, nullptr);

    // emb needs key + removed
    cudaStreamWaitEvent(0, eRm, 0);
    k_emb<<<BSZ / 8, 256>>>(sel, entity_num, selnum);
    // u = relu(selemb@e1 + e1b)
    k_mma<64, 5><<<dim3((SEQN - 1) * BSZ / 64, DF / 64), 256>>>(
        (const float*)pSel, e1w, e1b, (float*)pU, DK, DF, nullptr, nullptr, nullptr, nullptr);
    // P = u@W2 + base + c2, relu -> g_R rows [512, 32768)
    cudaStreamWaitEvent(0, ePre, 0);
    k_mma<64, 4><<<dim3((SEQN - 1) * BSZ / 64, DF / 64), 256>>>(
        (const float*)pU, (const float*)pW2, nullptr, nullptr, DF, DF,
        (const float*)pBase, (const float*)pC2, nullptr, (float*)pR);
    // fused x GEMM + gates LN
    k_xgx<<<SEQN * BSZ / 128, 256>>>((const float*)pR, q2w, q2b, wih, ln_ig, ln_ib);
    // lstm + logits
    k_lstm<<<BSZ / 8, 256>>>(whh, ln_hg, ln_hb, ln_cg, ln_cb);
    k_logits<<<BSZ, 256>>>(entity_num, out);
    (void)in_sizes;
    (void)n_in;
    (void)out_size;
}

// round 7
// speedup vs baseline: 2.0393x; 1.1833x over previous
#include <cuda_runtime.h>
#include <math.h>
#include <stdint.h>

#define BSZ 512
#define ENT 512
#define SEQN 64
#define DK 32
#define DF 256
#define DIN 1024
#define NGATE 128
#define ENP1 513

typedef unsigned long long u64;

// ----------------------------- static scratch --------------------------------
__device__ float g_key[(size_t)BSZ * ENT * DK];
__device__ int   g_removed[(size_t)BSZ * ENP1];
__device__ float g_selemb[(size_t)SEQN * BSZ * DK];
__device__ float g_base[(size_t)BSZ * DF];
__device__ float g_W2[(size_t)DF * DF];
__device__ float g_c2[DF];
__device__ float g_gx[(size_t)SEQN * BSZ * NGATE];
__device__ float g_q[(size_t)SEQN * BSZ * DK];

// ----------------------------- helpers ---------------------------------------
__device__ __forceinline__ float wredsum(float v) {
#pragma unroll
    for (int o = 16; o; o >>= 1) v += __shfl_xor_sync(0xffffffffu, v, o);
    return v;
}
__device__ __forceinline__ void fma2(u64& d, u64 a, u64 b) {
    asm("fma.rn.f32x2 %0,%1,%2,%0;" : "+l"(d) : "l"(a), "l"(b));
}
__device__ __forceinline__ float2 up2(u64 v) {
    float2 f;
    asm("mov.b64 {%0,%1},%2;" : "=f"(f.x), "=f"(f.y) : "l"(v));
    return f;
}
__device__ __forceinline__ uint32_t f2tf(float f) {
    uint32_t r;
    asm("cvt.rna.tf32.f32 %0, %1;" : "=r"(r) : "f"(f));
    return r;
}
__device__ __forceinline__ void mma_tf32(float* c, uint32_t a0, uint32_t a1, uint32_t a2,
                                         uint32_t a3, uint32_t b0, uint32_t b1) {
    asm volatile(
        "mma.sync.aligned.m16n8k8.row.col.f32.tf32.tf32.f32 "
        "{%0,%1,%2,%3},{%4,%5,%6,%7},{%8,%9},{%0,%1,%2,%3};"
        : "+f"(c[0]), "+f"(c[1]), "+f"(c[2]), "+f"(c[3])
        : "r"(a0), "r"(a1), "r"(a2), "r"(a3), "r"(b0), "r"(b1));
}

// --------------- tf32 tensor-core GEMM (standalone) ---------------------------
// EPI: 0 plain | 1 +bias | 2 +bias & end-scatter (key)
template <int BN, int EPI>
__global__ void k_mma(const float* __restrict__ A, const float* __restrict__ B,
                      const float* __restrict__ bias, float* __restrict__ C,
                      int K, int N, const float* __restrict__ xb,
                      const int* __restrict__ xi) {
    constexpr int BM = 64, KC = 32;
    constexpr int NBLD = (KC * BN) / 1024;
    constexpr int NT = BN / 16;
    __shared__ uint32_t As[BM][KC + 4];
    __shared__ uint32_t Bs[KC][BN + 4];
    const int t = threadIdx.x;
    const int wid = t >> 5, lane = t & 31;
    const int gid = lane >> 2, tig = lane & 3;
    const int warpM = wid & 3, warpN = wid >> 2;
    const int m0 = blockIdx.x * BM;
    const int n0 = blockIdx.y * BN;

    float cr[NT][4];
#pragma unroll
    for (int j = 0; j < NT; j++) {
        cr[j][0] = 0.f; cr[j][1] = 0.f; cr[j][2] = 0.f; cr[j][3] = 0.f;
    }

    const int ar0 = t >> 3;
    const int ak = (t & 7) * 4;
    constexpr int BQ = BN / 4;
    const int br0 = t / BQ;
    const int bn = (t % BQ) * 4;

    float4 pa0, pa1, pb[NBLD];
    pa0 = *(const float4*)&A[(size_t)(m0 + ar0) * K + ak];
    pa1 = *(const float4*)&A[(size_t)(m0 + ar0 + 32) * K + ak];
#pragma unroll
    for (int i = 0; i < NBLD; i++) {
        int kr = br0 + i * (256 / BQ);
        pb[i] = *(const float4*)&B[(size_t)kr * N + n0 + bn];
    }

    const int nch = K / KC;
    for (int ch = 0; ch < nch; ch++) {
        __syncthreads();
        {
            uint4 q;
            q.x = f2tf(pa0.x); q.y = f2tf(pa0.y); q.z = f2tf(pa0.z); q.w = f2tf(pa0.w);
            *(uint4*)&As[ar0][ak] = q;
            q.x = f2tf(pa1.x); q.y = f2tf(pa1.y); q.z = f2tf(pa1.z); q.w = f2tf(pa1.w);
            *(uint4*)&As[ar0 + 32][ak] = q;
#pragma unroll
            for (int i = 0; i < NBLD; i++) {
                int kr = br0 + i * (256 / BQ);
                q.x = f2tf(pb[i].x); q.y = f2tf(pb[i].y);
                q.z = f2tf(pb[i].z); q.w = f2tf(pb[i].w);
                *(uint4*)&Bs[kr][bn] = q;
            }
        }
        if (ch + 1 < nch) {
            int k0 = (ch + 1) * KC;
            pa0 = *(const float4*)&A[(size_t)(m0 + ar0) * K + k0 + ak];
            pa1 = *(const float4*)&A[(size_t)(m0 + ar0 + 32) * K + k0 + ak];
#pragma unroll
            for (int i = 0; i < NBLD; i++) {
                int kr = k0 + br0 + i * (256 / BQ);
                pb[i] = *(const float4*)&B[(size_t)kr * N + n0 + bn];
            }
        }
        __syncthreads();
#pragma unroll
        for (int kk = 0; kk < KC; kk += 8) {
            uint32_t a0 = As[warpM * 16 + gid][kk + tig];
            uint32_t a1 = As[warpM * 16 + gid + 8][kk + tig];
            uint32_t a2 = As[warpM * 16 + gid][kk + tig + 4];
            uint32_t a3 = As[warpM * 16 + gid + 8][kk + tig + 4];
#pragma unroll
            for (int j = 0; j < NT; j++) {
                int nb = warpN * (BN / 2) + j * 8;
                uint32_t b0 = Bs[kk + tig][nb + gid];
                uint32_t b1 = Bs[kk + tig + 4][nb + gid];
                mma_tf32(cr[j], a0, a1, a2, a3, b0, b1);
            }
        }
    }

    const int rb = m0 + warpM * 16 + gid;
#pragma unroll
    for (int j = 0; j < NT; j++) {
        int cb = n0 + warpN * (BN / 2) + j * 8 + tig * 2;
#pragma unroll
        for (int h = 0; h < 2; h++) {
            int m = rb + h * 8;
            float v0 = cr[j][h * 2 + 0];
            float v1 = cr[j][h * 2 + 1];
            if (EPI == 0) {
                C[(size_t)m * N + cb] = v0;
                C[(size_t)m * N + cb + 1] = v1;
            } else if (EPI == 1) {
                C[(size_t)m * N + cb] = v0 + bias[cb];
                C[(size_t)m * N + cb + 1] = v1 + bias[cb + 1];
            } else if (EPI == 2) {
                int en = xi[m0 >> 9];
                if ((m & 511) == en) {
                    C[(size_t)m * N + cb] = xb[cb];
                    C[(size_t)m * N + cb + 1] = xb[cb + 1];
                } else {
                    C[(size_t)m * N + cb] = v0 + bias[cb];
                    C[(size_t)m * N + cb + 1] = v1 + bias[cb + 1];
                }
            }
        }
    }
}

// --------------- mega-fused: selemb -> u -> P -> relu -> x -> LN gates --------
// One block = 64 rows of the step-major [SEQN*BSZ] space (all rows in one step).
// smem layout (floats):
//  U/Rtile (tf32 u32) [64][260]      @ 0        (16640)
//  Bs (W2 chunk tf32) 2x[32][264]    @ 16640    (16896)   } phase2 aliases:
//     q2s [256][40] @16640, xsh [64][33] @26880, wih @28992 (4096)
//  E1 (tf32) [32][264]               @ 33536    (8448)
//  SEL (tf32) [64][36]               @ 41984    (2304)
#define SMF 44288
__global__ void __launch_bounds__(256, 1)
k_fused(const float* __restrict__ e1w, const float* __restrict__ e1b,
        const float* __restrict__ q2w, const float* __restrict__ q2b,
        const float* __restrict__ wih, const float* __restrict__ ln_ig,
        const float* __restrict__ ln_ib) {
    extern __shared__ float sm[];
    uint32_t* U = (uint32_t*)sm;
    uint32_t* BSb = (uint32_t*)(sm + 16640);
    uint32_t* Q2S = (uint32_t*)(sm + 16640);
    float* xsh = sm + 26880;
    float* wsh = sm + 28992;
    uint32_t* E1 = (uint32_t*)(sm + 33536);
    uint32_t* SEL = (uint32_t*)(sm + 41984);

    const int t = threadIdx.x;
    const int wid = t >> 5, lane = t & 31;
    const int gid = lane >> 2, tig = lane & 3;
    const int warpM = wid & 3, warpN = wid >> 2;
    const int m0 = blockIdx.x * 64;
    const int step = m0 >> 9;
    const int b0 = m0 & 511;

    if (step == 0) {
        // Rtile = tf32(relu(base))
        for (int idx = t; idx < 64 * 256; idx += 256) {
            int r = idx >> 8, c = idx & 255;
            U[r * 260 + c] = f2tf(fmaxf(g_base[(size_t)(b0 + r) * 256 + c], 0.f));
        }
    } else {
        // ---- stage selemb (step-1 rows) and e1w as tf32 ----
        for (int idx = t; idx < 512; idx += 256) {
            int r = idx >> 3, c4 = (idx & 7) * 4;
            float4 v = *(const float4*)&g_selemb[(size_t)(m0 - 512 + r) * 32 + c4];
            SEL[r * 36 + c4 + 0] = f2tf(v.x);
            SEL[r * 36 + c4 + 1] = f2tf(v.y);
            SEL[r * 36 + c4 + 2] = f2tf(v.z);
            SEL[r * 36 + c4 + 3] = f2tf(v.w);
        }
        for (int idx = t; idx < 2048; idx += 256) {
            int r = idx >> 6, c4 = (idx & 63) * 4;
            float4 v = *(const float4*)&e1w[(size_t)r * 256 + c4];
            E1[r * 264 + c4 + 0] = f2tf(v.x);
            E1[r * 264 + c4 + 1] = f2tf(v.y);
            E1[r * 264 + c4 + 2] = f2tf(v.z);
            E1[r * 264 + c4 + 3] = f2tf(v.w);
        }
        __syncthreads();

        float acc[16][4];
#pragma unroll
        for (int j = 0; j < 16; j++) {
            acc[j][0] = 0.f; acc[j][1] = 0.f; acc[j][2] = 0.f; acc[j][3] = 0.f;
        }
        // ---- u = selemb @ e1 (K=32) ----
#pragma unroll
        for (int kk = 0; kk < 32; kk += 8) {
            uint32_t a0 = SEL[(warpM * 16 + gid) * 36 + kk + tig];
            uint32_t a1 = SEL[(warpM * 16 + gid + 8) * 36 + kk + tig];
            uint32_t a2 = SEL[(warpM * 16 + gid) * 36 + kk + tig + 4];
            uint32_t a3 = SEL[(warpM * 16 + gid + 8) * 36 + kk + tig + 4];
#pragma unroll
            for (int j = 0; j < 16; j++) {
                int nb = warpN * 128 + j * 8;
                uint32_t b0 = E1[(kk + tig) * 264 + nb + gid];
                uint32_t b1 = E1[(kk + tig + 4) * 264 + nb + gid];
                mma_tf32(acc[j], a0, a1, a2, a3, b0, b1);
            }
        }
        // relu(+e1b) -> U (tf32)
#pragma unroll
        for (int j = 0; j < 16; j++) {
            int cb = warpN * 128 + j * 8 + tig * 2;
            float bb0 = e1b[cb], bb1 = e1b[cb + 1];
#pragma unroll
            for (int h = 0; h < 2; h++) {
                int r = warpM * 16 + gid + h * 8;
                U[r * 260 + cb] = f2tf(fmaxf(acc[j][h * 2] + bb0, 0.f));
                U[r * 260 + cb + 1] = f2tf(fmaxf(acc[j][h * 2 + 1] + bb1, 0.f));
            }
        }
        // zero accumulators for P
#pragma unroll
        for (int j = 0; j < 16; j++) {
            acc[j][0] = 0.f; acc[j][1] = 0.f; acc[j][2] = 0.f; acc[j][3] = 0.f;
        }
        // ---- P = u @ W2 (K=256, stream W2 in 32-k chunks, double buffered) ----
        const int br = t >> 3;           // 0..31 rows of chunk
        const int bc4 = (t & 7) * 4;     // wait: need 64 float4 per row
        // per-thread W2 loads: 8 float4 covering [32][256]
        float4 pw[8];
#pragma unroll
        for (int p = 0; p < 8; p++) {
            int idx = t + p * 256;
            int r = idx >> 6, c4 = (idx & 63) * 4;
            pw[p] = *(const float4*)&g_W2[(size_t)r * 256 + c4];
        }
        (void)br; (void)bc4;
        for (int ch = 0; ch < 8; ch++) {
            int buf = ch & 1;
            uint32_t* BS = BSb + buf * 8448;
#pragma unroll
            for (int p = 0; p < 8; p++) {
                int idx = t + p * 256;
                int r = idx >> 6, c4 = (idx & 63) * 4;
                BS[r * 264 + c4 + 0] = f2tf(pw[p].x);
                BS[r * 264 + c4 + 1] = f2tf(pw[p].y);
                BS[r * 264 + c4 + 2] = f2tf(pw[p].z);
                BS[r * 264 + c4 + 3] = f2tf(pw[p].w);
            }
            if (ch + 1 < 8) {
#pragma unroll
                for (int p = 0; p < 8; p++) {
                    int idx = t + p * 256;
                    int r = idx >> 6, c4 = (idx & 63) * 4;
                    pw[p] = *(const float4*)&g_W2[(size_t)((ch + 1) * 32 + r) * 256 + c4];
                }
            }
            __syncthreads();
#pragma unroll
            for (int kk = 0; kk < 32; kk += 8) {
                int kg = ch * 32 + kk;
                uint32_t a0 = U[(warpM * 16 + gid) * 260 + kg + tig];
                uint32_t a1 = U[(warpM * 16 + gid + 8) * 260 + kg + tig];
                uint32_t a2 = U[(warpM * 16 + gid) * 260 + kg + tig + 4];
                uint32_t a3 = U[(warpM * 16 + gid + 8) * 260 + kg + tig + 4];
#pragma unroll
                for (int j = 0; j < 16; j++) {
                    int nb = warpN * 128 + j * 8;
                    uint32_t b0 = BS[(kk + tig) * 264 + nb + gid];
                    uint32_t b1 = BS[(kk + tig + 4) * 264 + nb + gid];
                    mma_tf32(acc[j], a0, a1, a2, a3, b0, b1);
                }
            }
            __syncthreads();
        }
        // ---- pre = P + base + c2, relu -> Rtile (overwrite U) ----
#pragma unroll
        for (int j = 0; j < 16; j++) {
            int cb = warpN * 128 + j * 8 + tig * 2;
            float cc0 = g_c2[cb], cc1 = g_c2[cb + 1];
#pragma unroll
            for (int h = 0; h < 2; h++) {
                int r = warpM * 16 + gid + h * 8;
                float bs0 = g_base[(size_t)(b0 + r) * 256 + cb];
                float bs1 = g_base[(size_t)(b0 + r) * 256 + cb + 1];
                U[r * 260 + cb] = f2tf(fmaxf(acc[j][h * 2] + bs0 + cc0, 0.f));
                U[r * 260 + cb + 1] = f2tf(fmaxf(acc[j][h * 2 + 1] + bs1 + cc1, 0.f));
            }
        }
    }
    __syncthreads();

    // ---- stage q2 (tf32) + wih ----
    for (int idx = t; idx < 2048; idx += 256) {
        int r = idx >> 3, c4 = (idx & 7) * 4;
        float4 v = *(const float4*)&q2w[(size_t)r * 32 + c4];
        Q2S[r * 40 + c4 + 0] = f2tf(v.x);
        Q2S[r * 40 + c4 + 1] = f2tf(v.y);
        Q2S[r * 40 + c4 + 2] = f2tf(v.z);
        Q2S[r * 40 + c4 + 3] = f2tf(v.w);
    }
    for (int idx = t; idx < 4096; idx += 256) wsh[idx] = wih[idx];
    __syncthreads();

    // ---- x = Rtile @ q2 (K=256, N=32) ----
    {
        float ax[2][4];
        ax[0][0] = ax[0][1] = ax[0][2] = ax[0][3] = 0.f;
        ax[1][0] = ax[1][1] = ax[1][2] = ax[1][3] = 0.f;
#pragma unroll 4
        for (int kk = 0; kk < 256; kk += 8) {
            uint32_t a0 = U[(warpM * 16 + gid) * 260 + kk + tig];
            uint32_t a1 = U[(warpM * 16 + gid + 8) * 260 + kk + tig];
            uint32_t a2 = U[(warpM * 16 + gid) * 260 + kk + tig + 4];
            uint32_t a3 = U[(warpM * 16 + gid + 8) * 260 + kk + tig + 4];
#pragma unroll
            for (int j = 0; j < 2; j++) {
                int nb = warpN * 16 + j * 8;
                uint32_t b0 = Q2S[(kk + tig) * 40 + nb + gid];
                uint32_t b1 = Q2S[(kk + tig + 4) * 40 + nb + gid];
                mma_tf32(ax[j], a0, a1, a2, a3, b0, b1);
            }
        }
        __syncthreads();
#pragma unroll
        for (int j = 0; j < 2; j++) {
            int cb = warpN * 16 + j * 8 + tig * 2;
            float qb0 = q2b[cb], qb1 = q2b[cb + 1];
#pragma unroll
            for (int h = 0; h < 2; h++) {
                int r = warpM * 16 + gid + h * 8;
                xsh[r * 33 + cb] = ax[j][h * 2] + qb0;
                xsh[r * 33 + cb + 1] = ax[j][h * 2 + 1] + qb1;
            }
        }
    }
    __syncthreads();

    // ---- gates = LN(x @ wih) ----
    {
        int w = wid;
        float lg[4], lb[4];
#pragma unroll
        for (int g = 0; g < 4; g++) {
            lg[g] = ln_ig[g * 32 + lane];
            lb[g] = ln_ib[g * 32 + lane];
        }
        for (int rr = 0; rr < 8; rr++) {
            int row = rr * 8 + w;
            float xv = xsh[row * 33 + lane];
            float acg[4] = {0.f, 0.f, 0.f, 0.f};
#pragma unroll
            for (int k = 0; k < 32; k++) {
                float xk = __shfl_sync(0xffffffffu, xv, k);
#pragma unroll
                for (int g = 0; g < 4; g++) acg[g] += xk * wsh[k * 128 + g * 32 + lane];
            }
            float s = acg[0] + acg[1] + acg[2] + acg[3];
            float m = wredsum(s) * (1.f / 128.f);
            float vs = 0.f;
#pragma unroll
            for (int g = 0; g < 4; g++) {
                float d = acg[g] - m;
                vs += d * d;
            }
            float v = wredsum(vs) * (1.f / 128.f);
            float rs = rsqrtf(v + 1e-5f);
#pragma unroll
            for (int g = 0; g < 4; g++)
                g_gx[(size_t)(m0 + row) * 128 + g * 32 + lane] =
                    (acg[g] - m) * rs * lg[g] + lb[g];
        }
    }
}

// ------------------- first-removal-step scatter --------------------------------
__global__ void k_removed(const int* __restrict__ sel) {
    int b = blockIdx.x;
    for (int n = threadIdx.x; n < ENP1; n += blockDim.x) g_removed[(size_t)b * ENP1 + n] = 65;
    __syncthreads();
    if (threadIdx.x < SEQN) {
        int s = sel[b * SEQN + threadIdx.x];
        atomicMin(&g_removed[(size_t)b * ENP1 + s], threadIdx.x + 1);
    }
}

// ------------------- per-step pooled embedding ---------------------------------
__global__ void k_emb(const int* __restrict__ sel, const int* __restrict__ en_arr,
                      const int* __restrict__ selnum) {
    int t = threadIdx.x;
    int lane = t & 31;
    int b = blockIdx.x * 8 + (t >> 5);
    int en = en_arr[b];
    int sn = selnum[b];
    int s0 = sel[b * SEQN + lane];
    int s1 = sel[b * SEQN + 32 + lane];
    int sc = __shfl_sync(0xffffffffu, s0, 0);
    float kv_n = g_key[((size_t)b * ENT + sc) * DK + lane];
    int rm_n = g_removed[(size_t)b * ENP1 + sc];
    float sum = 0.f;
    int cnt = 0;
    bool endf = false;
    for (int j = 0; j < SEQN; j++) {
        float kv = kv_n;
        int rm = rm_n;
        int s = (j < 32) ? __shfl_sync(0xffffffffu, s0, j) : __shfl_sync(0xffffffffu, s1, j - 32);
        if (j + 1 < SEQN) {
            int s2 = (j + 1 < 32) ? __shfl_sync(0xffffffffu, s0, j + 1)
                                  : __shfl_sync(0xffffffffu, s1, j - 31);
            kv_n = g_key[((size_t)b * ENT + s2) * DK + lane];
            rm_n = g_removed[(size_t)b * ENP1 + s2];
        }
        endf = endf || (s == en);
        if ((!endf) && rm == j + 1) {
            sum += kv;
            cnt++;
        }
        float denom = (sn != 0 && cnt > 0) ? (float)cnt : 1.f;
        g_selemb[((size_t)j * BSZ + b) * DK + lane] = sum / denom;
    }
}

// ------------------- c2 = e2_b @ q1_w ------------------------------------------
__global__ void k_c2(const float* __restrict__ e2b, const float* __restrict__ q1w) {
    int t = threadIdx.x;
    float acc = 0.f;
    for (int k = 0; k < DIN; k++) acc += e2b[k] * q1w[(size_t)k * DF + t];
    g_c2[t] = acc;
}

// ------------------- sequential LN-LSTM (warp/batch) ---------------------------
__global__ void k_lstm(const float* __restrict__ whh, const float* __restrict__ ln_hg,
                       const float* __restrict__ ln_hb, const float* __restrict__ ln_cg,
                       const float* __restrict__ ln_cb) {
    __shared__ float wsh[32 * 128];
    int t = threadIdx.x;
    for (int idx = t; idx < 4096; idx += 256) wsh[idx] = whh[idx];
    __syncthreads();
    int lane = t & 31, w = t >> 5;
    int b = blockIdx.x * 8 + w;
    float h = 0.f, c = 0.f;
    float hg[4], hb[4];
#pragma unroll
    for (int g = 0; g < 4; g++) {
        int cc = g * 32 + lane;
        hg[g] = ln_hg[cc];
        hb[g] = ln_hb[cc];
    }
    float cgm = ln_cg[lane], cbm = ln_cb[lane];
    float gxr[4];
#pragma unroll
    for (int g = 0; g < 4; g++) gxr[g] = g_gx[(size_t)b * 128 + g * 32 + lane];
    for (int i = 0; i < SEQN; i++) {
        float gxn[4];
        if (i + 1 < SEQN) {
            size_t rn = (size_t)(i + 1) * BSZ + b;
#pragma unroll
            for (int g = 0; g < 4; g++) gxn[g] = g_gx[rn * 128 + g * 32 + lane];
        }
        float acc[4] = {0.f, 0.f, 0.f, 0.f};
#pragma unroll
        for (int k = 0; k < 32; k++) {
            float hk = __shfl_sync(0xffffffffu, h, k);
#pragma unroll
            for (int g = 0; g < 4; g++) acc[g] += hk * wsh[k * 128 + g * 32 + lane];
        }
        float s = acc[0] + acc[1] + acc[2] + acc[3];
        float m = wredsum(s) * (1.f / 128.f);
        float vs = 0.f;
#pragma unroll
        for (int g = 0; g < 4; g++) {
            float d = acc[g] - m;
            vs += d * d;
        }
        float v = wredsum(vs) * (1.f / 128.f);
        float rs = rsqrtf(v + 1e-5f);
        float gate[4];
#pragma unroll
        for (int g = 0; g < 4; g++) gate[g] = gxr[g] + (acc[g] - m) * rs * hg[g] + hb[g];
        float ii = 1.f / (1.f + __expf(-gate[0]));
        float ff = 1.f / (1.f + __expf(-gate[1]));
        float gg = tanhf(gate[2]);
        float oo = 1.f / (1.f + __expf(-gate[3]));
        float cn = ff * c + ii * gg;
        float mc = wredsum(cn) * (1.f / 32.f);
        float dc = cn - mc;
        float vc = wredsum(dc * dc) * (1.f / 32.f);
        c = dc * rsqrtf(vc + 1e-5f) * cgm + cbm;
        h = oo * tanhf(c);
        g_q[((size_t)i * BSZ + b) * DK + lane] = h;
#pragma unroll
        for (int g = 0; g < 4; g++) gxr[g] = gxn[g];
    }
}

// ------------------- logits + mask (grid BSZ x 2) -------------------------------
__global__ void k_logits(const int* __restrict__ en_arr, float* __restrict__ out) {
    __shared__ float Qsh[64 * 32];
    __shared__ float Ksh[256 * 34];
    __shared__ int rsh[256];
    typedef unsigned long long u64l;
    int t = threadIdx.x;
    int b = blockIdx.x;
    int tile = blockIdx.y;
    int en = en_arr[b];
    for (int idx = t; idx < 2048; idx += 256) {
        int s = idx >> 5, k = idx & 31;
        Qsh[idx] = g_q[((size_t)s * BSZ + b) * 32 + k];
    }
    const u64l* Q2 = (const u64l*)Qsh;
    int n0 = tile * 256;
    for (int idx = t; idx < 8192; idx += 256) {
        int n = idx >> 5, k = idx & 31;
        Ksh[n * 34 + k] = g_key[((size_t)b * ENT + n0 + n) * 32 + k];
    }
    rsh[t] = g_removed[(size_t)b * ENP1 + n0 + t];
    __syncthreads();
    u64l kreg[16];
#pragma unroll
    for (int kp = 0; kp < 16; kp++) {
        float2 kk = *(const float2*)&Ksh[t * 34 + kp * 2];
        asm("mov.b64 %0,{%1,%2};" : "=l"(kreg[kp]) : "f"(kk.x), "f"(kk.y));
    }
    int rstep = rsh[t];
    int n = n0 + t;
    for (int s = 0; s < SEQN; s++) {
        u64l a0 = 0ull, a1 = 0ull;
#pragma unroll
        for (int kp = 0; kp < 16; kp += 2) {
            fma2(a0, kreg[kp], Q2[s * 16 + kp]);
            fma2(a1, kreg[kp + 1], Q2[s * 16 + kp + 1]);
        }
        float2 f0 = up2(a0), f1 = up2(a1);
        float dot = (f0.x + f0.y) + (f1.x + f1.y);
        bool keep = (n < en) ? (rstep > s) : ((n == en) ? (s >= 1 && rstep > s) : false);
        out[((size_t)b * SEQN + s) * ENP1 + n] = keep ? dot : -1e9f;
    }
    if (tile == 1 && t < SEQN) out[((size_t)b * SEQN + t) * ENP1 + 512] = -1e9f;
}

// ------------------------------- launch ----------------------------------------
extern "C" void kernel_launch(void* const* d_in, const int* in_sizes, int n_in,
                              void* d_out, int out_size) {
    const float* ent = (const float*)d_in[0];
    const float* ar = (const float*)d_in[1];
    const int* entity_num = (const int*)d_in[2];
    const int* sel = (const int*)d_in[3];
    const int* selnum = (const int*)d_in[4];
    const float* key_w = (const float*)d_in[5];
    const float* key_b = (const float*)d_in[6];
    const float* q1w = (const float*)d_in[7];
    const float* q1b = (const float*)d_in[8];
    const float* q2w = (const float*)d_in[9];
    const float* q2b = (const float*)d_in[10];
    const float* e1w = (const float*)d_in[11];
    const float* e1b = (const float*)d_in[12];
    const float* e2w = (const float*)d_in[13];
    const float* e2b = (const float*)d_in[14];
    const float* endv = (const float*)d_in[15];
    const float* wih = (const float*)d_in[16];
    const float* whh = (const float*)d_in[17];
    const float* ln_ig = (const float*)d_in[18];
    const float* ln_ib = (const float*)d_in[19];
    const float* ln_hg = (const float*)d_in[20];
    const float* ln_hb = (const float*)d_in[21];
    const float* ln_cg = (const float*)d_in[22];
    const float* ln_cb = (const float*)d_in[23];
    float* out = (float*)d_out;

    void *pKey, *pBase, *pW2;
    cudaGetSymbolAddress(&pKey, g_key);
    cudaGetSymbolAddress(&pBase, g_base);
    cudaGetSymbolAddress(&pW2, g_W2);

    static cudaStream_t sA = 0, sB = 0, sC = 0;
    static cudaEvent_t eFork = 0, eRm = 0, eB = 0, eW2 = 0;
    if (!sA) {
        cudaStreamCreateWithFlags(&sA, cudaStreamNonBlocking);
        cudaStreamCreateWithFlags(&sB, cudaStreamNonBlocking);
        cudaStreamCreateWithFlags(&sC, cudaStreamNonBlocking);
        cudaEventCreateWithFlags(&eFork, cudaEventDisableTiming);
        cudaEventCreateWithFlags(&eRm, cudaEventDisableTiming);
        cudaEventCreateWithFlags(&eB, cudaEventDisableTiming);
        cudaEventCreateWithFlags(&eW2, cudaEventDisableTiming);
        cudaFuncSetAttribute(k_fused, cudaFuncAttributeMaxDynamicSharedMemorySize,
                             SMF * 4);
    }

    // fork
    cudaEventRecord(eFork, 0);
    cudaStreamWaitEvent(sA, eFork, 0);
    cudaStreamWaitEvent(sB, eFork, 0);
    cudaStreamWaitEvent(sC, eFork, 0);

    // side A: removal scatter
    k_removed<<<BSZ, 256, 0, sA>>>(sel);
    cudaEventRecord(eRm, sA);

    // side B: c2 + base
    k_c2<<<1, 256, 0, sB>>>(e2b, q1w);
    k_mma<64, 1><<<dim3(BSZ / 64, DF / 64), 256, 0, sB>>>(
        ar, q1w, q1b, (float*)pBase, DIN, DF, nullptr, nullptr);
    cudaEventRecord(eB, sB);

    // side C: W2 = e2 @ q1
    k_mma<64, 0><<<dim3(DF / 64, DF / 64), 256, 0, sC>>>(
        e2w, q1w, nullptr, (float*)pW2, DIN, DF, nullptr, nullptr);
    cudaEventRecord(eW2, sC);

    // main: key GEMM (overlaps side streams)
    k_mma<32, 2><<<dim3(BSZ * ENT / 64, 1), 256>>>(
        ent, key_w, key_b, (float*)pKey, DF, DK, endv, entity_num);

    // emb needs key + removed
    cudaStreamWaitEvent(0, eRm, 0);
    k_emb<<<BSZ / 8, 256>>>(sel, entity_num, selnum);

    // fused chain needs selemb + base + c2 + W2
    cudaStreamWaitEvent(0, eB, 0);
    cudaStreamWaitEvent(0, eW2, 0);
    k_fused<<<SEQN * BSZ / 64, 256, SMF * 4>>>(e1w, e1b, q2w, q2b, wih, ln_ig, ln_ib);

    // lstm + logits
    k_lstm<<<BSZ / 8, 256>>>(whh, ln_hg, ln_hb, ln_cg, ln_cb);
    k_logits<<<dim3(BSZ, 2), 256>>>(entity_num, out);
    (void)in_sizes;
    (void)n_in;
    (void)out_size;
}